// round 1
// baseline (speedup 1.0000x reference)
#include <cuda_runtime.h>
#include <math.h>

#define NB 8
#define SEQ 256
#define DIM 512
#define NH 8
#define HDIM 64
#define NLAYER 4
#define ROWS (NB*SEQ)
#define NEGV -1e30f

// ---------------- static scratch (no allocation allowed) ----------------
__device__ float g_a  [ROWS*DIM];
__device__ float g_v  [ROWS*DIM];
__device__ float g_v2 [ROWS*DIM];
__device__ float g_q  [ROWS*DIM];
__device__ float g_k  [ROWS*DIM];
__device__ float g_vv [ROWS*DIM];
__device__ float g_ctx[ROWS*DIM];
__device__ float g_t  [ROWS*DIM];
__device__ float g_h  [ROWS*DIM*4];
__device__ float g_sc [NB*NH*SEQ*SEQ];
__device__ float g_sim[NB*SEQ*SEQ];

// ---------------- generic tiled GEMM ----------------
// C = act( alpha*A@B(^T) + bias + bias2 + beta*C + rscale*resid )
// batched: z -> (zo = z/inner, zi = z%inner); offset = zo*sXo + zi*sXi
template<int BM, int BN, int BK, int TM, int TN, bool TB>
__global__ void __launch_bounds__(256)
gemm_k(const float* __restrict__ A, const float* __restrict__ Bm,
       float* C,
       int M, int N, int K, int lda, int ldb, int ldc,
       long long sAo, long long sAi, long long sBo, long long sBi,
       long long sCo, long long sCi, int inner,
       float alpha, const float* __restrict__ bias, const float* __restrict__ bias2,
       const float* __restrict__ resid, float rscale, int beta, int act)
{
    int z  = blockIdx.z;
    int zo = z / inner, zi = z - zo * inner;
    A  += zo * sAo + zi * sAi;
    Bm += zo * sBo + zi * sBi;
    C  += zo * sCo + zi * sCi;
    if (resid) resid += zo * sCo + zi * sCi;

    __shared__ float As[BK][BM + 4];
    __shared__ float Bs[BK][BN + 4];

    int tid = threadIdx.x;
    int tx = tid & 15, ty = tid >> 4;
    int row0 = blockIdx.y * BM;
    int col0 = blockIdx.x * BN;

    float acc[TM][TN];
#pragma unroll
    for (int i = 0; i < TM; i++)
#pragma unroll
        for (int j = 0; j < TN; j++) acc[i][j] = 0.f;

    for (int k0 = 0; k0 < K; k0 += BK) {
        // A tile (BM x BK), stored transposed
#pragma unroll
        for (int idx = tid; idx < BM * BK / 4; idx += 256) {
            int r  = idx / (BK / 4);
            int kq = idx % (BK / 4);
            float4 va = *(const float4*)&A[(long long)(row0 + r) * lda + k0 + kq * 4];
            As[kq*4+0][r] = va.x; As[kq*4+1][r] = va.y;
            As[kq*4+2][r] = va.z; As[kq*4+3][r] = va.w;
        }
        if (!TB) {
#pragma unroll
            for (int idx = tid; idx < BK * BN / 4; idx += 256) {
                int kk = idx / (BN / 4);
                int nq = idx % (BN / 4);
                *(float4*)&Bs[kk][nq * 4] =
                    *(const float4*)&Bm[(long long)(k0 + kk) * ldb + col0 + nq * 4];
            }
        } else {
#pragma unroll
            for (int idx = tid; idx < BN * BK / 4; idx += 256) {
                int r  = idx / (BK / 4);
                int kq = idx % (BK / 4);
                float4 vb = *(const float4*)&Bm[(long long)(col0 + r) * ldb + k0 + kq * 4];
                Bs[kq*4+0][r] = vb.x; Bs[kq*4+1][r] = vb.y;
                Bs[kq*4+2][r] = vb.z; Bs[kq*4+3][r] = vb.w;
            }
        }
        __syncthreads();
#pragma unroll
        for (int k = 0; k < BK; k++) {
            float af[TM], bf[TN];
#pragma unroll
            for (int i = 0; i < TM; i += 4) *(float4*)&af[i] = *(float4*)&As[k][ty * TM + i];
#pragma unroll
            for (int j = 0; j < TN; j += 4) *(float4*)&bf[j] = *(float4*)&Bs[k][tx * TN + j];
#pragma unroll
            for (int i = 0; i < TM; i++)
#pragma unroll
                for (int j = 0; j < TN; j++) acc[i][j] += af[i] * bf[j];
        }
        __syncthreads();
    }
#pragma unroll
    for (int i = 0; i < TM; i++) {
        int r = row0 + ty * TM + i;
#pragma unroll
        for (int j = 0; j < TN; j++) {
            int c = col0 + tx * TN + j;
            float val = alpha * acc[i][j];
            if (bias)  val += bias[c];
            if (bias2) val += bias2[c];
            long long off = (long long)r * ldc + c;
            if (beta)  val += C[off];
            if (resid) val += rscale * resid[off];
            if (act)   val = 0.5f * val * (1.f + erff(val * 0.70710678118654752f));
            C[off] = val;
        }
    }
}

// ---------------- softmax over 256-wide rows (in place) ----------------
__global__ void softmax256_k(float* x)
{
    __shared__ float red[8];
    __shared__ float bc[2];
    int t = threadIdx.x;
    float* p = x + (long long)blockIdx.x * 256;
    float v = p[t];
    float m = v;
#pragma unroll
    for (int o = 16; o; o >>= 1) m = fmaxf(m, __shfl_xor_sync(0xffffffffu, m, o));
    if ((t & 31) == 0) red[t >> 5] = m;
    __syncthreads();
    if (t == 0) { float mm = red[0]; for (int i = 1; i < 8; i++) mm = fmaxf(mm, red[i]); bc[0] = mm; }
    __syncthreads();
    float e = expf(v - bc[0]);
    float s = e;
#pragma unroll
    for (int o = 16; o; o >>= 1) s += __shfl_xor_sync(0xffffffffu, s, o);
    if ((t & 31) == 0) red[t >> 5] = s;
    __syncthreads();
    if (t == 0) { float tt = 0.f; for (int i = 0; i < 8; i++) tt += red[i]; bc[1] = 1.f / tt; }
    __syncthreads();
    p[t] = e * bc[1];
}

// ---------------- LayerNorm over 512-wide rows: y = LN(x (+ r)) * g + b ----------------
__global__ void ln512_k(const float* __restrict__ x, const float* r,
                        float* y, const float* __restrict__ g, const float* __restrict__ bb)
{
    __shared__ float red[8];
    __shared__ float bc;
    long long row = blockIdx.x;
    int t = threadIdx.x;
    const float* px = x + row * 512;
    float v0 = px[t], v1 = px[t + 256];
    if (r) { const float* pr = r + row * 512; v0 += pr[t]; v1 += pr[t + 256]; }
    float s = v0 + v1;
#pragma unroll
    for (int o = 16; o; o >>= 1) s += __shfl_xor_sync(0xffffffffu, s, o);
    if ((t & 31) == 0) red[t >> 5] = s;
    __syncthreads();
    if (t == 0) { float tt = 0.f; for (int i = 0; i < 8; i++) tt += red[i]; bc = tt * (1.f / 512.f); }
    __syncthreads();
    float mean = bc;
    float d0 = v0 - mean, d1 = v1 - mean;
    float q = d0 * d0 + d1 * d1;
#pragma unroll
    for (int o = 16; o; o >>= 1) q += __shfl_xor_sync(0xffffffffu, q, o);
    if ((t & 31) == 0) red[t >> 5] = q;
    __syncthreads();
    if (t == 0) { float tt = 0.f; for (int i = 0; i < 8; i++) tt += red[i]; bc = tt * (1.f / 512.f); }
    __syncthreads();
    float inv = rsqrtf(bc + 1e-5f);
    float* py = y + row * 512;
    py[t]       = d0 * inv * g[t]       + bb[t];
    py[t + 256] = d1 * inv * g[t + 256] + bb[t + 256];
}

// ---------------- row-wise L2 normalize (512 wide, in place) ----------------
__global__ void l2n_k(float* x)
{
    __shared__ float red[8];
    __shared__ float bc;
    long long row = blockIdx.x;
    int t = threadIdx.x;
    float* p = x + row * 512;
    float v0 = p[t], v1 = p[t + 256];
    float q = v0 * v0 + v1 * v1;
#pragma unroll
    for (int o = 16; o; o >>= 1) q += __shfl_xor_sync(0xffffffffu, q, o);
    if ((t & 31) == 0) red[t >> 5] = q;
    __syncthreads();
    if (t == 0) { float tt = 0.f; for (int i = 0; i < 8; i++) tt += red[i];
                  bc = 1.f / fmaxf(sqrtf(tt), 1e-12f); }
    __syncthreads();
    p[t]       = v0 * bc;
    p[t + 256] = v1 * bc;
}

// ---------------- DTW wavefront DP ----------------
// dp[i][j] = sim[i-1][j-1] + max(dp[i-1][j], dp[i][j-1], dp[i-1][j-1]); score = dp[256][256]
__global__ void dtw_k(const float* __restrict__ sim, float* score)
{
    __shared__ float buf[3][SEQ + 1];
    int b = blockIdx.x;
    const float* S = sim + (long long)b * SEQ * SEQ;
    int t = threadIdx.x;
    float *dm2 = buf[0], *dm1 = buf[1], *dc = buf[2];
    if (t == 0) { buf[0][0] = 0.f; buf[1][0] = NEGV; buf[1][1] = NEGV; }
    __syncthreads();
    for (int td = 2; td <= 2 * SEQ; td++) {
        int i = t + 1;
        int j = td - i;
        float val = 0.f;
        bool active = (j >= 1 && j <= SEQ);
        if (active) {
            float dg = dm2[i - 1];
            float up = dm1[i - 1];
            float lf = dm1[i];
            val = S[(i - 1) * SEQ + (j - 1)] + fmaxf(dg, fmaxf(up, lf));
            dc[i] = val;
        }
        if (t == 0 && td <= SEQ) { dc[0] = NEGV; dc[td] = NEGV; }
        if (td == 2 * SEQ && i == SEQ) score[b] = val;
        __syncthreads();
        float* tmp = dm2; dm2 = dm1; dm1 = dc; dc = tmp;
    }
}

// ---------------- host-side launch helpers ----------------
static void gemm(const float* A, const float* Bm, float* C,
                 int M, int N, int K, int lda, int ldb, int ldc,
                 long long sAo, long long sAi, long long sBo, long long sBi,
                 long long sCo, long long sCi, int inner, int batch,
                 float alpha, const float* bias, const float* bias2,
                 const float* resid, float rs, int beta, int act, bool tb)
{
    if (tb) {
        dim3 g(N / 64, M / 64, batch);
        gemm_k<64,64,16,4,4,true><<<g,256>>>(A,Bm,C,M,N,K,lda,ldb,ldc,
            sAo,sAi,sBo,sBi,sCo,sCi,inner,alpha,bias,bias2,resid,rs,beta,act);
    } else if (M % 128 == 0 && N % 128 == 0) {
        dim3 g(N / 128, M / 128, batch);
        gemm_k<128,128,8,8,8,false><<<g,256>>>(A,Bm,C,M,N,K,lda,ldb,ldc,
            sAo,sAi,sBo,sBi,sCo,sCi,inner,alpha,bias,bias2,resid,rs,beta,act);
    } else {
        dim3 g(N / 64, M / 64, batch);
        gemm_k<64,64,16,4,4,false><<<g,256>>>(A,Bm,C,M,N,K,lda,ldb,ldc,
            sAo,sAi,sBo,sBi,sCo,sCi,inner,alpha,bias,bias2,resid,rs,beta,act);
    }
}

static void gemm_plain(const float* A, const float* Bm, float* C, int M, int N, int K,
                       float alpha, const float* bias, const float* bias2, int beta, int act)
{
    gemm(A, Bm, C, M, N, K, K, N, N, 0,0,0,0,0,0, 1, 1,
         alpha, bias, bias2, nullptr, 0.f, beta, act, false);
}

extern "C" void kernel_launch(void* const* d_in, const int* in_sizes, int n_in,
                              void* d_out, int out_size)
{
    const float* audio  = (const float*)d_in[0];
    const float* video  = (const float*)d_in[1];
    const float* ap_w   = (const float*)d_in[2];
    const float* ap_b   = (const float*)d_in[3];
    const float* vp_w   = (const float*)d_in[4];
    const float* vp_b   = (const float*)d_in[5];
    const float* dtw_w  = (const float*)d_in[6];
    const float* dtw_b  = (const float*)d_in[7];
    const float* mod_emb= (const float*)d_in[8];
    const float* ca_w   = (const float*)d_in[9];
    const float* ca_b   = (const float*)d_in[10];
    const float* sa_w   = (const float*)d_in[11];
    const float* sa_b   = (const float*)d_in[12];
    const float* ln_g   = (const float*)d_in[13];
    const float* ln_b   = (const float*)d_in[14];
    const float* ffn_w1 = (const float*)d_in[15];
    const float* ffn_b1 = (const float*)d_in[16];
    const float* ffn_w2 = (const float*)d_in[17];
    const float* ffn_b2 = (const float*)d_in[18];
    const float* out_w  = (const float*)d_in[19];
    const float* out_b  = (const float*)d_in[20];
    const float* fln_g  = (const float*)d_in[21];
    const float* fln_b  = (const float*)d_in[22];

    float *pa,*pv,*pv2,*pq,*pk,*pvv,*pctx,*pt,*ph,*psc,*psim;
    cudaGetSymbolAddress((void**)&pa,  g_a);
    cudaGetSymbolAddress((void**)&pv,  g_v);
    cudaGetSymbolAddress((void**)&pv2, g_v2);
    cudaGetSymbolAddress((void**)&pq,  g_q);
    cudaGetSymbolAddress((void**)&pk,  g_k);
    cudaGetSymbolAddress((void**)&pvv, g_vv);
    cudaGetSymbolAddress((void**)&pctx,g_ctx);
    cudaGetSymbolAddress((void**)&pt,  g_t);
    cudaGetSymbolAddress((void**)&ph,  g_h);
    cudaGetSymbolAddress((void**)&psc, g_sc);
    cudaGetSymbolAddress((void**)&psim,g_sim);

    float* out = (float*)d_out;
    float* out_score = out + (out_size - NB);

    const long long SD  = (long long)SEQ * DIM;   // per-batch activation stride
    const long long SS  = (long long)SEQ * SEQ;   // per-(b,h) score stride

    // ---- projections + modality embeddings ----
    gemm_plain(audio, ap_w, pa, ROWS, DIM, DIM, 1.f, ap_b, mod_emb,        0, 0);
    gemm_plain(video, vp_w, pv, ROWS, DIM, 256, 1.f, vp_b, mod_emb + DIM,  0, 0);

    // ---- DTW similarity ----
    gemm_plain(pa, dtw_w, pq, ROWS, DIM, DIM, 1.f, dtw_b, nullptr, 0, 0);
    gemm_plain(pv, dtw_w, pk, ROWS, DIM, DIM, 1.f, dtw_b, nullptr, 0, 0);
    l2n_k<<<ROWS,256>>>(pq);
    l2n_k<<<ROWS,256>>>(pk);
    // sim[b] = an[b] @ vn[b]^T   (NT, batched over b)
    gemm(pq, pk, psim, SEQ, SEQ, DIM, DIM, DIM, SEQ,
         SD, 0, SD, 0, SS, 0, 1, NB,
         1.f, nullptr, nullptr, nullptr, 0.f, 0, 0, true);
    dtw_k<<<NB,256>>>(psim, out_score);
    // alignment: v2 = 0.5*v + 0.5*softmax(sim) @ v
    softmax256_k<<<NB*SEQ,256>>>(psim);
    gemm(psim, pv, pv2, SEQ, DIM, SEQ, SEQ, DIM, DIM,
         SS, 0, SD, 0, SD, 0, 1, NB,
         0.5f, nullptr, nullptr, pv, 0.5f, 0, 0, false);

    float* a = pa;
    float* v = pv2;

    auto mha = [&](float* x, const float* kv, const float* W, const float* bb,
                   const float* lg, const float* lb) {
        gemm_plain(x,  W,             pq,  ROWS, DIM, DIM, 1.f, bb,         nullptr, 0, 0);
        gemm_plain(kv, W + DIM*DIM,   pk,  ROWS, DIM, DIM, 1.f, bb + DIM,   nullptr, 0, 0);
        gemm_plain(kv, W + 2*DIM*DIM, pvv, ROWS, DIM, DIM, 1.f, bb + 2*DIM, nullptr, 0, 0);
        // scores[b,h] = (1/8) * Q_bh @ K_bh^T
        gemm(pq, pk, psc, SEQ, SEQ, HDIM, DIM, DIM, SEQ,
             SD, HDIM, SD, HDIM, (long long)NH*SS, SS, NH, NB*NH,
             0.125f, nullptr, nullptr, nullptr, 0.f, 0, 0, true);
        softmax256_k<<<NB*NH*SEQ,256>>>(psc);
        // ctx[b,h] = P @ V_bh
        gemm(psc, pvv, pctx, SEQ, HDIM, SEQ, SEQ, DIM, DIM,
             (long long)NH*SS, SS, SD, HDIM, SD, HDIM, NH, NB*NH,
             1.f, nullptr, nullptr, nullptr, 0.f, 0, 0, false);
        gemm_plain(pctx, W + 3*DIM*DIM, pt, ROWS, DIM, DIM, 1.f, bb + 3*DIM, nullptr, 0, 0);
        ln512_k<<<ROWS,256>>>(pt, x, x, lg, lb);
    };

    auto ffn = [&](float* x, const float* w1, const float* b1,
                   const float* w2, const float* b2,
                   const float* lg, const float* lb) {
        gemm_plain(x,  w1, ph, ROWS, 4*DIM, DIM,   1.f, b1, nullptr, 0, 1);  // GELU epilogue
        gemm_plain(ph, w2, pt, ROWS, DIM,   4*DIM, 1.f, b2, nullptr, 0, 0);
        ln512_k<<<ROWS,256>>>(pt, x, x, lg, lb);
    };

    for (int l = 0; l < NLAYER; l++) {
        const float* caw0 = ca_w + (long long)((l*2+0)*4) * DIM * DIM;
        const float* caw1 = ca_w + (long long)((l*2+1)*4) * DIM * DIM;
        const float* cab0 = ca_b + (long long)((l*2+0)*4) * DIM;
        const float* cab1 = ca_b + (long long)((l*2+1)*4) * DIM;
        const float* saw0 = sa_w + (long long)((l*2+0)*4) * DIM * DIM;
        const float* saw1 = sa_w + (long long)((l*2+1)*4) * DIM * DIM;
        const float* sab0 = sa_b + (long long)((l*2+0)*4) * DIM;
        const float* sab1 = sa_b + (long long)((l*2+1)*4) * DIM;
        const float* lg = ln_g + (long long)l * 6 * DIM;
        const float* lb = ln_b + (long long)l * 6 * DIM;

        mha(a, v, caw0, cab0, lg + 0*DIM, lb + 0*DIM);      // a cross-attends v
        mha(v, a, caw1, cab1, lg + 3*DIM, lb + 3*DIM);      // v cross-attends (updated) a
        mha(a, a, saw0, sab0, lg + 1*DIM, lb + 1*DIM);      // a self
        mha(v, v, saw1, sab1, lg + 4*DIM, lb + 4*DIM);      // v self
        ffn(a, ffn_w1 + (long long)(l*2+0)*DIM*4*DIM, ffn_b1 + (long long)(l*2+0)*4*DIM,
               ffn_w2 + (long long)(l*2+0)*4*DIM*DIM, ffn_b2 + (long long)(l*2+0)*DIM,
               lg + 2*DIM, lb + 2*DIM);
        ffn(v, ffn_w1 + (long long)(l*2+1)*DIM*4*DIM, ffn_b1 + (long long)(l*2+1)*4*DIM,
               ffn_w2 + (long long)(l*2+1)*4*DIM*DIM, ffn_b2 + (long long)(l*2+1)*DIM,
               lg + 5*DIM, lb + 5*DIM);
    }

    // ---- fused head: [a | v] @ out_w + out_b, then LN -> d_out ----
    gemm_plain(a, out_w,            pq, ROWS, DIM, DIM, 1.f, nullptr, nullptr, 0, 0);
    gemm_plain(v, out_w + DIM*DIM,  pq, ROWS, DIM, DIM, 1.f, out_b,   nullptr, 1, 0);
    ln512_k<<<ROWS,256>>>(pq, nullptr, out, fln_g, fln_b);
}

// round 3
// speedup vs baseline: 3.9956x; 3.9956x over previous
#include <cuda_runtime.h>
#include <cuda_bf16.h>
#include <math.h>
#include <stdint.h>

#define NB 8
#define SEQ 256
#define DIM 512
#define NH 8
#define HDIM 64
#define NLAYER 4
#define ROWS (NB*SEQ)
#define NEGV -1e30f

typedef __nv_bfloat16 bf16;
typedef __nv_bfloat162 bf162;

// ---------------- static scratch (no allocation allowed) ----------------
__device__ float g_a  [ROWS*DIM];
__device__ float g_v  [ROWS*DIM];
__device__ float g_v2 [ROWS*DIM];
__device__ float g_q  [ROWS*DIM];
__device__ float g_k  [ROWS*DIM];
__device__ float g_vv [ROWS*DIM];
__device__ float g_ctx[ROWS*DIM];
__device__ float g_t  [ROWS*DIM];
__device__ float g_h  [ROWS*DIM*4];
__device__ float g_sc [NB*NH*SEQ*SEQ];
__device__ float g_sim[NB*SEQ*SEQ];

// bf16 hi/lo mirrors of activations
__device__ bf16 m_audh[ROWS*DIM],  m_audl[ROWS*DIM];
__device__ bf16 m_vidh[ROWS*256],  m_vidl[ROWS*256];
__device__ bf16 m_ah[ROWS*DIM],    m_al[ROWS*DIM];
__device__ bf16 m_vh[ROWS*DIM],    m_vl[ROWS*DIM];
__device__ bf16 m_qh[ROWS*DIM],    m_ql[ROWS*DIM];
__device__ bf16 m_kh[ROWS*DIM],    m_kl[ROWS*DIM];
__device__ bf16 m_vvTh[NB*DIM*SEQ],m_vvTl[NB*DIM*SEQ];
__device__ bf16 m_pvTh[NB*DIM*SEQ],m_pvTl[NB*DIM*SEQ];
__device__ bf16 m_ctxh[ROWS*DIM],  m_ctxl[ROWS*DIM];
__device__ bf16 m_hh[ROWS*DIM*4],  m_hl[ROWS*DIM*4];
__device__ bf16 m_sch[NB*NH*SEQ*SEQ], m_scl[NB*NH*SEQ*SEQ];
__device__ bf16 m_simh[NB*SEQ*SEQ],   m_siml[NB*SEQ*SEQ];

// transposed bf16 weights: [N][K] layout
// w512T holds 68 mats of 512x512: [0]=ap_w [1]=dtw_w [2..3]=out_w halves [4..35]=ca_w [36..67]=sa_w
__device__ bf16 w512Th[68*512*512], w512Tl[68*512*512];
__device__ bf16 wvpTh[512*256],     wvpTl[512*256];
__device__ bf16 wf1Th[8*2048*512],  wf1Tl[8*2048*512];
__device__ bf16 wf2Th[8*512*2048],  wf2Tl[8*512*2048];

// ---------------- PTX helpers ----------------
__device__ __forceinline__ uint32_t smem_u32(const void* p) {
    return (uint32_t)__cvta_generic_to_shared(p);
}
__device__ __forceinline__ void cp16(uint32_t so, const void* g) {
    asm volatile("cp.async.cg.shared.global [%0], [%1], 16;" :: "r"(so), "l"(g));
}
__device__ __forceinline__ void ldm4(uint32_t* r, uint32_t addr) {
    asm volatile("ldmatrix.sync.aligned.m8n8.x4.shared.b16 {%0,%1,%2,%3}, [%4];"
        : "=r"(r[0]), "=r"(r[1]), "=r"(r[2]), "=r"(r[3]) : "r"(addr));
}
__device__ __forceinline__ void mma16816(float* d, const uint32_t* a, const uint32_t* b) {
    asm volatile(
        "mma.sync.aligned.m16n8k16.row.col.f32.bf16.bf16.f32 "
        "{%0,%1,%2,%3}, {%4,%5,%6,%7}, {%8,%9}, {%0,%1,%2,%3};"
        : "+f"(d[0]), "+f"(d[1]), "+f"(d[2]), "+f"(d[3])
        : "r"(a[0]), "r"(a[1]), "r"(a[2]), "r"(a[3]), "r"(b[0]), "r"(b[1]));
}

// ---------------- HMMA GEMM: C = act(alpha*(Ah+Al)@(Bh+Bl)^T + bias(+bias2) + beta*C + rscale*resid) ----------------
// A: [M][K] K-major bf16 hi/lo, B: [N][K] K-major bf16 hi/lo. acc = Ah*Bh + Ah*Bl + Al*Bh (fp32).
// Tiles: BM x BN x 32. Warps: NWM x NWN, warp tile (BM/NWM=32) x (BN/NWN).
template<int BM, int BN, int NWM, int NWN>
__global__ void __launch_bounds__(NWM*NWN*32)
mma_gemm(const bf16* __restrict__ Ah_, const bf16* __restrict__ Al_,
         const bf16* __restrict__ Bh_, const bf16* __restrict__ Bl_,
         float* __restrict__ C,
         int K, int lda, int ldb, int ldc,
         long long sAo, long long sAi, long long sBo, long long sBi,
         long long sCo, long long sCi, int inner,
         float alpha, const float* __restrict__ bias, const float* __restrict__ bias2,
         const float* __restrict__ resid, float rscale, int beta, int act,
         bf16* outh, bf16* outl)
{
    constexpr int TH = NWM * NWN * 32;
    constexpr int WN = BN / NWN;      // warp n extent
    constexpr int NF = WN / 8;        // n fragments per warp
    constexpr int ACH = BM * 4;       // 16B chunks per A array per stage
    constexpr int BCH = BN * 4;
    constexpr int STAGE = (BM + BN) * 128;  // bytes per stage (hi+lo, A+B)
    // stage layout: [Ah BM*64][Al BM*64][Bh BN*64][Bl BN*64]

    extern __shared__ char smem[];
    uint32_t sb = smem_u32(smem);

    int z = blockIdx.z, zo = z / inner, zi = z - zo * inner;
    long long aoff = zo * sAo + zi * sAi;
    long long boff = zo * sBo + zi * sBi;
    Ah_ += aoff; Al_ += aoff;
    Bh_ += boff; Bl_ += boff;
    long long coff = zo * sCo + zi * sCi;
    C += coff;
    if (resid) resid += coff;
    if (outh) { outh += coff; outl += coff; }

    int tid = threadIdx.x, wid = tid >> 5, lane = tid & 31;
    int wm = wid % NWM, wn = wid / NWM;
    int row0 = blockIdx.y * BM, col0 = blockIdx.x * BN;

    auto loadStage = [&](int k0, int s) {
        uint32_t sbase = sb + s * STAGE;
#pragma unroll
        for (int idx = tid; idx < ACH; idx += TH) {
            int r = idx >> 2, c = idx & 3;
            int cs = c ^ ((r >> 1) & 3);
            uint32_t so = sbase + (uint32_t)(r * 4 + cs) * 16;
            long long g = (long long)(row0 + r) * lda + k0 + c * 8;
            cp16(so,            Ah_ + g);
            cp16(so + BM * 64,  Al_ + g);
        }
#pragma unroll
        for (int idx = tid; idx < BCH; idx += TH) {
            int r = idx >> 2, c = idx & 3;
            int cs = c ^ ((r >> 1) & 3);
            uint32_t so = sbase + BM * 128 + (uint32_t)(r * 4 + cs) * 16;
            long long g = (long long)(col0 + r) * ldb + k0 + c * 8;
            cp16(so,            Bh_ + g);
            cp16(so + BN * 64,  Bl_ + g);
        }
        asm volatile("cp.async.commit_group;");
    };

    float acc[2][NF][4];
#pragma unroll
    for (int i = 0; i < 2; i++)
#pragma unroll
        for (int j = 0; j < NF; j++)
#pragma unroll
            for (int q = 0; q < 4; q++) acc[i][j][q] = 0.f;

    int nch = K / 32;
    loadStage(0, 0);
    for (int s = 0; s < nch; s++) {
        if (s + 1 < nch) {
            loadStage((s + 1) * 32, (s + 1) & 1);
            asm volatile("cp.async.wait_group 1;");
        } else {
            asm volatile("cp.async.wait_group 0;");
        }
        __syncthreads();
        uint32_t sbase = sb + (s & 1) * STAGE;
#pragma unroll
        for (int ks = 0; ks < 2; ks++) {
            uint32_t ah[2][4], al[2][4];
#pragma unroll
            for (int mf = 0; mf < 2; mf++) {
                int row = wm * 32 + mf * 16 + (lane & 15);
                int c = ks * 2 + (lane >> 4);
                int cs = c ^ ((row >> 1) & 3);
                uint32_t ad = sbase + (uint32_t)(row * 4 + cs) * 16;
                ldm4(ah[mf], ad);
                ldm4(al[mf], ad + BM * 64);
            }
            uint32_t bh[NF][2], bl[NF][2];
#pragma unroll
            for (int nf = 0; nf < NF; nf += 2) {
                int rown = wn * WN + nf * 8 + (lane >> 4) * 8 + (lane & 7);
                int c = ks * 2 + ((lane >> 3) & 1);
                int cs = c ^ ((rown >> 1) & 3);
                uint32_t bd = sbase + BM * 128 + (uint32_t)(rown * 4 + cs) * 16;
                uint32_t t[4];
                ldm4(t, bd);
                bh[nf][0] = t[0]; bh[nf][1] = t[1]; bh[nf+1][0] = t[2]; bh[nf+1][1] = t[3];
                ldm4(t, bd + BN * 64);
                bl[nf][0] = t[0]; bl[nf][1] = t[1]; bl[nf+1][0] = t[2]; bl[nf+1][1] = t[3];
            }
#pragma unroll
            for (int mf = 0; mf < 2; mf++)
#pragma unroll
                for (int nf = 0; nf < NF; nf++) {
                    mma16816(acc[mf][nf], ah[mf], bh[nf]);
                    mma16816(acc[mf][nf], ah[mf], bl[nf]);
                    mma16816(acc[mf][nf], al[mf], bh[nf]);
                }
        }
        __syncthreads();
    }

    // ---- epilogue ----
    auto epi2 = [&](int r, int c, float v0, float v1) {
        long long off = (long long)r * ldc + c;
        v0 *= alpha; v1 *= alpha;
        if (bias)  { float2 b2 = *(const float2*)&bias[c];  v0 += b2.x; v1 += b2.y; }
        if (bias2) { float2 b2 = *(const float2*)&bias2[c]; v0 += b2.x; v1 += b2.y; }
        if (beta)  { float2 c2 = *(const float2*)&C[off];   v0 += c2.x; v1 += c2.y; }
        if (resid) { float2 r2 = *(const float2*)&resid[off]; v0 += rscale * r2.x; v1 += rscale * r2.y; }
        if (act) {
            v0 = 0.5f * v0 * (1.f + erff(v0 * 0.70710678118654752f));
            v1 = 0.5f * v1 * (1.f + erff(v1 * 0.70710678118654752f));
        }
        *(float2*)&C[off] = make_float2(v0, v1);
        if (outh) {
            bf16 h0 = __float2bfloat16(v0), h1 = __float2bfloat16(v1);
            *(bf162*)&outh[off] = bf162(h0, h1);
            *(bf162*)&outl[off] = bf162(__float2bfloat16(v0 - __bfloat162float(h0)),
                                        __float2bfloat16(v1 - __bfloat162float(h1)));
        }
    };
#pragma unroll
    for (int mf = 0; mf < 2; mf++) {
        int r0 = row0 + wm * 32 + mf * 16 + (lane >> 2);
#pragma unroll
        for (int nf = 0; nf < NF; nf++) {
            int c = col0 + wn * WN + nf * 8 + (lane & 3) * 2;
            epi2(r0,     c, acc[mf][nf][0], acc[mf][nf][1]);
            epi2(r0 + 8, c, acc[mf][nf][2], acc[mf][nf][3]);
        }
    }
}

// ---------------- converts ----------------
__global__ void cvt_k(const float* __restrict__ x, bf16* __restrict__ h, bf16* __restrict__ l, int n)
{
    int i = blockIdx.x * 256 + threadIdx.x;
    if (i < n) {
        float v = x[i];
        bf16 hh = __float2bfloat16(v);
        h[i] = hh;
        l[i] = __float2bfloat16(v - __bfloat162float(hh));
    }
}

// transpose-convert per batch: src [b][R][C] fp32 -> out [b][C][R] bf16 hi/lo
__global__ void tcvt_k(const float* __restrict__ src, bf16* __restrict__ oh, bf16* __restrict__ ol, int R, int C)
{
    __shared__ float t[32][33];
    long long bo = (long long)blockIdx.z * R * C;
    src += bo; oh += bo; ol += bo;
    int c0 = blockIdx.x * 32, r0 = blockIdx.y * 32;
    int tx = threadIdx.x, ty = threadIdx.y;
#pragma unroll
    for (int i = ty; i < 32; i += 8)
        t[i][tx] = src[(long long)(r0 + i) * C + c0 + tx];
    __syncthreads();
#pragma unroll
    for (int i = ty; i < 32; i += 8) {
        float v = t[tx][i];
        bf16 hh = __float2bfloat16(v);
        long long o = (long long)(c0 + i) * R + r0 + tx;
        oh[o] = hh;
        ol[o] = __float2bfloat16(v - __bfloat162float(hh));
    }
}

// ---------------- softmax over 256-wide rows -> bf16 hi/lo mirrors ----------------
__global__ void softmax256_k(const float* __restrict__ x, bf16* __restrict__ oh, bf16* __restrict__ ol)
{
    __shared__ float red[8];
    __shared__ float bc[2];
    int t = threadIdx.x;
    const float* p = x + (long long)blockIdx.x * 256;
    float v = p[t];
    float m = v;
#pragma unroll
    for (int o = 16; o; o >>= 1) m = fmaxf(m, __shfl_xor_sync(0xffffffffu, m, o));
    if ((t & 31) == 0) red[t >> 5] = m;
    __syncthreads();
    if (t == 0) { float mm = red[0]; for (int i = 1; i < 8; i++) mm = fmaxf(mm, red[i]); bc[0] = mm; }
    __syncthreads();
    float e = expf(v - bc[0]);
    float s = e;
#pragma unroll
    for (int o = 16; o; o >>= 1) s += __shfl_xor_sync(0xffffffffu, s, o);
    if ((t & 31) == 0) red[t >> 5] = s;
    __syncthreads();
    if (t == 0) { float tt = 0.f; for (int i = 0; i < 8; i++) tt += red[i]; bc[1] = 1.f / tt; }
    __syncthreads();
    float val = e * bc[1];
    long long o = (long long)blockIdx.x * 256 + t;
    bf16 hh = __float2bfloat16(val);
    oh[o] = hh;
    ol[o] = __float2bfloat16(val - __bfloat162float(hh));
}

// ---------------- LayerNorm 512 wide: y = LN(x (+ r)) * g + b, optional bf16 mirrors ----------------
__global__ void ln512_k(const float* __restrict__ x, const float* r,
                        float* y, const float* __restrict__ g, const float* __restrict__ bb,
                        bf16* oh, bf16* ol)
{
    __shared__ float red[8];
    __shared__ float bc;
    long long row = blockIdx.x;
    int t = threadIdx.x;
    const float* px = x + row * 512;
    float v0 = px[t], v1 = px[t + 256];
    if (r) { const float* pr = r + row * 512; v0 += pr[t]; v1 += pr[t + 256]; }
    float s = v0 + v1;
#pragma unroll
    for (int o = 16; o; o >>= 1) s += __shfl_xor_sync(0xffffffffu, s, o);
    if ((t & 31) == 0) red[t >> 5] = s;
    __syncthreads();
    if (t == 0) { float tt = 0.f; for (int i = 0; i < 8; i++) tt += red[i]; bc = tt * (1.f / 512.f); }
    __syncthreads();
    float mean = bc;
    float d0 = v0 - mean, d1 = v1 - mean;
    float q = d0 * d0 + d1 * d1;
#pragma unroll
    for (int o = 16; o; o >>= 1) q += __shfl_xor_sync(0xffffffffu, q, o);
    if ((t & 31) == 0) red[t >> 5] = q;
    __syncthreads();
    if (t == 0) { float tt = 0.f; for (int i = 0; i < 8; i++) tt += red[i]; bc = tt * (1.f / 512.f); }
    __syncthreads();
    float inv = rsqrtf(bc + 1e-5f);
    float y0 = d0 * inv * g[t]       + bb[t];
    float y1 = d1 * inv * g[t + 256] + bb[t + 256];
    float* py = y + row * 512;
    py[t] = y0;  py[t + 256] = y1;
    if (oh) {
        bf16 h0 = __float2bfloat16(y0), h1 = __float2bfloat16(y1);
        oh[row * 512 + t] = h0;       ol[row * 512 + t] = __float2bfloat16(y0 - __bfloat162float(h0));
        oh[row * 512 + t + 256] = h1; ol[row * 512 + t + 256] = __float2bfloat16(y1 - __bfloat162float(h1));
    }
}

// ---------------- L2 normalize 512-wide, writes fp32 in place + bf16 mirrors ----------------
__global__ void l2n_k(float* x, bf16* oh, bf16* ol)
{
    __shared__ float red[8];
    __shared__ float bc;
    long long row = blockIdx.x;
    int t = threadIdx.x;
    float* p = x + row * 512;
    float v0 = p[t], v1 = p[t + 256];
    float q = v0 * v0 + v1 * v1;
#pragma unroll
    for (int o = 16; o; o >>= 1) q += __shfl_xor_sync(0xffffffffu, q, o);
    if ((t & 31) == 0) red[t >> 5] = q;
    __syncthreads();
    if (t == 0) { float tt = 0.f; for (int i = 0; i < 8; i++) tt += red[i];
                  bc = 1.f / fmaxf(sqrtf(tt), 1e-12f); }
    __syncthreads();
    v0 *= bc; v1 *= bc;
    p[t] = v0; p[t + 256] = v1;
    bf16 h0 = __float2bfloat16(v0), h1 = __float2bfloat16(v1);
    oh[row * 512 + t] = h0;       ol[row * 512 + t] = __float2bfloat16(v0 - __bfloat162float(h0));
    oh[row * 512 + t + 256] = h1; ol[row * 512 + t + 256] = __float2bfloat16(v1 - __bfloat162float(h1));
}

// ---------------- DTW wavefront DP ----------------
__global__ void dtw_k(const float* __restrict__ sim, float* score)
{
    __shared__ float buf[3][SEQ + 1];
    int b = blockIdx.x;
    const float* S = sim + (long long)b * SEQ * SEQ;
    int t = threadIdx.x;
    float *dm2 = buf[0], *dm1 = buf[1], *dc = buf[2];
    if (t == 0) { buf[0][0] = 0.f; buf[1][0] = NEGV; buf[1][1] = NEGV; }
    __syncthreads();
    for (int td = 2; td <= 2 * SEQ; td++) {
        int i = t + 1;
        int j = td - i;
        float val = 0.f;
        bool active = (j >= 1 && j <= SEQ);
        if (active) {
            float dg = dm2[i - 1];
            float up = dm1[i - 1];
            float lf = dm1[i];
            val = S[(i - 1) * SEQ + (j - 1)] + fmaxf(dg, fmaxf(up, lf));
            dc[i] = val;
        }
        if (t == 0 && td <= SEQ) { dc[0] = NEGV; dc[td] = NEGV; }
        if (td == 2 * SEQ && i == SEQ) score[b] = val;
        __syncthreads();
        float* tmp = dm2; dm2 = dm1; dm1 = dc; dc = tmp;
    }
}

// ---------------- host-side launch helper ----------------
static void tcg(const bf16* Ah, const bf16* Al, const bf16* Bh, const bf16* Bl,
                float* C, int M, int N, int K, int lda, int ldb, int ldc,
                long long sAo, long long sAi, long long sBo, long long sBi,
                long long sCo, long long sCi, int inner, int batch,
                float alpha, const float* bias, const float* bias2,
                const float* resid, float rs, int beta, int act,
                bf16* outh, bf16* outl)
{
    if (N % 128 == 0) {
        long long c128 = (long long)(M / 128) * (N / 128) * batch;
        if (M % 128 == 0 && c128 >= 120) {
            constexpr int SM = (128 + 128) * 128 * 2;
            cudaFuncSetAttribute(mma_gemm<128,128,4,2>, cudaFuncAttributeMaxDynamicSharedMemorySize, SM);
            mma_gemm<128,128,4,2><<<dim3(N/128, M/128, batch), 256, SM>>>(
                Ah, Al, Bh, Bl, C, K, lda, ldb, ldc,
                sAo, sAi, sBo, sBi, sCo, sCi, inner, alpha, bias, bias2, resid, rs, beta, act, outh, outl);
        } else {
            constexpr int SM = (64 + 128) * 128 * 2;
            cudaFuncSetAttribute(mma_gemm<64,128,2,2>, cudaFuncAttributeMaxDynamicSharedMemorySize, SM);
            mma_gemm<64,128,2,2><<<dim3(N/128, M/64, batch), 128, SM>>>(
                Ah, Al, Bh, Bl, C, K, lda, ldb, ldc,
                sAo, sAi, sBo, sBi, sCo, sCi, inner, alpha, bias, bias2, resid, rs, beta, act, outh, outl);
        }
    } else {
        constexpr int SM = (128 + 64) * 128 * 2;
        cudaFuncSetAttribute(mma_gemm<128,64,4,2>, cudaFuncAttributeMaxDynamicSharedMemorySize, SM);
        mma_gemm<128,64,4,2><<<dim3(N/64, M/128, batch), 256, SM>>>(
            Ah, Al, Bh, Bl, C, K, lda, ldb, ldc,
            sAo, sAi, sBo, sBi, sCo, sCi, inner, alpha, bias, bias2, resid, rs, beta, act, outh, outl);
    }
}

static void tcg_plain(const bf16* Ah, const bf16* Al, const bf16* Bh, const bf16* Bl,
                      float* C, int M, int N, int K,
                      float alpha, const float* bias, const float* bias2, int beta, int act,
                      bf16* outh, bf16* outl)
{
    tcg(Ah, Al, Bh, Bl, C, M, N, K, K, K, N, 0, 0, 0, 0, 0, 0, 1, 1,
        alpha, bias, bias2, nullptr, 0.f, beta, act, outh, outl);
}

extern "C" void kernel_launch(void* const* d_in, const int* in_sizes, int n_in,
                              void* d_out, int out_size)
{
    const float* audio  = (const float*)d_in[0];
    const float* video  = (const float*)d_in[1];
    const float* ap_w   = (const float*)d_in[2];
    const float* ap_b   = (const float*)d_in[3];
    const float* vp_w   = (const float*)d_in[4];
    const float* vp_b   = (const float*)d_in[5];
    const float* dtw_w  = (const float*)d_in[6];
    const float* dtw_b  = (const float*)d_in[7];
    const float* mod_emb= (const float*)d_in[8];
    const float* ca_w   = (const float*)d_in[9];
    const float* ca_b   = (const float*)d_in[10];
    const float* sa_w   = (const float*)d_in[11];
    const float* sa_b   = (const float*)d_in[12];
    const float* ln_g   = (const float*)d_in[13];
    const float* ln_b   = (const float*)d_in[14];
    const float* ffn_w1 = (const float*)d_in[15];
    const float* ffn_b1 = (const float*)d_in[16];
    const float* ffn_w2 = (const float*)d_in[17];
    const float* ffn_b2 = (const float*)d_in[18];
    const float* out_w  = (const float*)d_in[19];
    const float* out_b  = (const float*)d_in[20];
    const float* fln_g  = (const float*)d_in[21];
    const float* fln_b  = (const float*)d_in[22];

    float *pa,*pv,*pv2,*pq,*pk,*pvv,*pctx,*pt,*ph,*psc,*psim;
    cudaGetSymbolAddress((void**)&pa,  g_a);
    cudaGetSymbolAddress((void**)&pv,  g_v);
    cudaGetSymbolAddress((void**)&pv2, g_v2);
    cudaGetSymbolAddress((void**)&pq,  g_q);
    cudaGetSymbolAddress((void**)&pk,  g_k);
    cudaGetSymbolAddress((void**)&pvv, g_vv);
    cudaGetSymbolAddress((void**)&pctx,g_ctx);
    cudaGetSymbolAddress((void**)&pt,  g_t);
    cudaGetSymbolAddress((void**)&ph,  g_h);
    cudaGetSymbolAddress((void**)&psc, g_sc);
    cudaGetSymbolAddress((void**)&psim,g_sim);

    bf16 *audh,*audl,*vidh,*vidl,*ah,*al,*vh,*vl,*qh,*ql,*kh,*kl;
    bf16 *vvTh,*vvTl,*pvTh,*pvTl,*ctxh,*ctxl,*hh,*hl,*sch,*scl,*simh,*siml;
    bf16 *w512h,*w512l,*vph,*vpl,*f1h,*f1l,*f2h,*f2l;
    cudaGetSymbolAddress((void**)&audh, m_audh); cudaGetSymbolAddress((void**)&audl, m_audl);
    cudaGetSymbolAddress((void**)&vidh, m_vidh); cudaGetSymbolAddress((void**)&vidl, m_vidl);
    cudaGetSymbolAddress((void**)&ah, m_ah);     cudaGetSymbolAddress((void**)&al, m_al);
    cudaGetSymbolAddress((void**)&vh, m_vh);     cudaGetSymbolAddress((void**)&vl, m_vl);
    cudaGetSymbolAddress((void**)&qh, m_qh);     cudaGetSymbolAddress((void**)&ql, m_ql);
    cudaGetSymbolAddress((void**)&kh, m_kh);     cudaGetSymbolAddress((void**)&kl, m_kl);
    cudaGetSymbolAddress((void**)&vvTh, m_vvTh); cudaGetSymbolAddress((void**)&vvTl, m_vvTl);
    cudaGetSymbolAddress((void**)&pvTh, m_pvTh); cudaGetSymbolAddress((void**)&pvTl, m_pvTl);
    cudaGetSymbolAddress((void**)&ctxh, m_ctxh); cudaGetSymbolAddress((void**)&ctxl, m_ctxl);
    cudaGetSymbolAddress((void**)&hh, m_hh);     cudaGetSymbolAddress((void**)&hl, m_hl);
    cudaGetSymbolAddress((void**)&sch, m_sch);   cudaGetSymbolAddress((void**)&scl, m_scl);
    cudaGetSymbolAddress((void**)&simh, m_simh); cudaGetSymbolAddress((void**)&siml, m_siml);
    cudaGetSymbolAddress((void**)&w512h, w512Th); cudaGetSymbolAddress((void**)&w512l, w512Tl);
    cudaGetSymbolAddress((void**)&vph, wvpTh);    cudaGetSymbolAddress((void**)&vpl, wvpTl);
    cudaGetSymbolAddress((void**)&f1h, wf1Th);    cudaGetSymbolAddress((void**)&f1l, wf1Tl);
    cudaGetSymbolAddress((void**)&f2h, wf2Th);    cudaGetSymbolAddress((void**)&f2l, wf2Tl);

    float* out = (float*)d_out;
    float* out_score = out + (out_size - NB);

    const long long SD = (long long)SEQ * DIM;
    const long long SS = (long long)SEQ * SEQ;
    const long long W  = (long long)DIM * DIM;   // 262144

    // ---- weight transpose-converts ([K][N] -> [N][K] bf16 hi/lo) ----
    {
        dim3 b32(32, 8);
        tcvt_k<<<dim3(512/32, 512/32, 1),  b32>>>(ap_w,  w512h + 0*W, w512l + 0*W, 512, 512);
        tcvt_k<<<dim3(512/32, 512/32, 1),  b32>>>(dtw_w, w512h + 1*W, w512l + 1*W, 512, 512);
        tcvt_k<<<dim3(512/32, 512/32, 2),  b32>>>(out_w, w512h + 2*W, w512l + 2*W, 512, 512);
        tcvt_k<<<dim3(512/32, 512/32, 32), b32>>>(ca_w,  w512h + 4*W, w512l + 4*W, 512, 512);
        tcvt_k<<<dim3(512/32, 512/32, 32), b32>>>(sa_w,  w512h + 36*W, w512l + 36*W, 512, 512);
        tcvt_k<<<dim3(512/32, 256/32, 1),  b32>>>(vp_w,  vph, vpl, 256, 512);
        tcvt_k<<<dim3(2048/32, 512/32, 8), b32>>>(ffn_w1, f1h, f1l, 512, 2048);
        tcvt_k<<<dim3(512/32, 2048/32, 8), b32>>>(ffn_w2, f2h, f2l, 2048, 512);
        cvt_k<<<(ROWS*DIM + 255)/256, 256>>>(audio, audh, audl, ROWS*DIM);
        cvt_k<<<(ROWS*256 + 255)/256, 256>>>(video, vidh, vidl, ROWS*256);
    }

    // ---- projections + modality embeddings ----
    tcg_plain(audh, audl, w512h + 0*W, w512l + 0*W, pa, ROWS, DIM, DIM, 1.f, ap_b, mod_emb,       0, 0, ah, al);
    tcg_plain(vidh, vidl, vph, vpl,                 pv, ROWS, DIM, 256, 1.f, vp_b, mod_emb + DIM, 0, 0, vh, vl);

    // ---- DTW similarity ----
    tcg_plain(ah, al, w512h + 1*W, w512l + 1*W, pq, ROWS, DIM, DIM, 1.f, dtw_b, nullptr, 0, 0, nullptr, nullptr);
    tcg_plain(vh, vl, w512h + 1*W, w512l + 1*W, pk, ROWS, DIM, DIM, 1.f, dtw_b, nullptr, 0, 0, nullptr, nullptr);
    l2n_k<<<ROWS, 256>>>(pq, qh, ql);
    l2n_k<<<ROWS, 256>>>(pk, kh, kl);
    // sim[b] = an[b] @ vn[b]^T
    tcg(qh, ql, kh, kl, psim, SEQ, SEQ, DIM, DIM, DIM, SEQ,
        SD, 0, SD, 0, SS, 0, 1, NB,
        1.f, nullptr, nullptr, nullptr, 0.f, 0, 0, nullptr, nullptr);
    dtw_k<<<NB, 256>>>(psim, out_score);
    softmax256_k<<<NB*SEQ, 256>>>(psim, simh, siml);
    // v2 = 0.5*v + 0.5*softmax(sim) @ v  (B = v transposed per batch)
    tcvt_k<<<dim3(512/32, 256/32, NB), dim3(32,8)>>>(pv, pvTh, pvTl, SEQ, DIM);
    tcg(simh, siml, pvTh, pvTl, pv2, SEQ, DIM, SEQ, SEQ, SEQ, DIM,
        SS, 0, (long long)DIM*SEQ, 0, SD, 0, 1, NB,
        0.5f, nullptr, nullptr, pv, 0.5f, 0, 0, vh, vl);

    float* a = pa;
    float* v = pv2;
    bf16 *a_h = ah, *a_l = al, *v_h = vh, *v_l = vl;

    auto mha = [&](float* x, bf16* x_h, bf16* x_l, bf16* kv_h, bf16* kv_l,
                   const bf16* Wh, const bf16* Wl, const float* bb,
                   const float* lg, const float* lb) {
        tcg_plain(x_h,  x_l,  Wh + 0*W, Wl + 0*W, pq,  ROWS, DIM, DIM, 1.f, bb,         nullptr, 0, 0, qh, ql);
        tcg_plain(kv_h, kv_l, Wh + 1*W, Wl + 1*W, pk,  ROWS, DIM, DIM, 1.f, bb + DIM,   nullptr, 0, 0, kh, kl);
        tcg_plain(kv_h, kv_l, Wh + 2*W, Wl + 2*W, pvv, ROWS, DIM, DIM, 1.f, bb + 2*DIM, nullptr, 0, 0, nullptr, nullptr);
        // scores[b,h] = (1/8) Q_bh @ K_bh^T
        tcg(qh, ql, kh, kl, psc, SEQ, SEQ, HDIM, DIM, DIM, SEQ,
            SD, HDIM, SD, HDIM, (long long)NH*SS, SS, NH, NB*NH,
            0.125f, nullptr, nullptr, nullptr, 0.f, 0, 0, nullptr, nullptr);
        softmax256_k<<<NB*NH*SEQ, 256>>>(psc, sch, scl);
        tcvt_k<<<dim3(512/32, 256/32, NB), dim3(32,8)>>>(pvv, vvTh, vvTl, SEQ, DIM);
        // ctx[b,h] = P @ V_bh   (B = vvT head rows)
        tcg(sch, scl, vvTh, vvTl, pctx, SEQ, HDIM, SEQ, SEQ, SEQ, DIM,
            (long long)NH*SS, SS, (long long)DIM*SEQ, (long long)HDIM*SEQ, SD, HDIM, NH, NB*NH,
            1.f, nullptr, nullptr, nullptr, 0.f, 0, 0, ctxh, ctxl);
        tcg_plain(ctxh, ctxl, Wh + 3*W, Wl + 3*W, pt, ROWS, DIM, DIM, 1.f, bb + 3*DIM, nullptr, 0, 0, nullptr, nullptr);
        ln512_k<<<ROWS, 256>>>(pt, x, x, lg, lb, x_h, x_l);
    };

    auto ffn = [&](float* x, bf16* x_h, bf16* x_l, int idx,
                   const float* lg, const float* lb) {
        const bf16* w1h = f1h + (long long)idx * 2048 * 512;
        const bf16* w1l = f1l + (long long)idx * 2048 * 512;
        const bf16* w2h = f2h + (long long)idx * 512 * 2048;
        const bf16* w2l = f2l + (long long)idx * 512 * 2048;
        tcg_plain(x_h, x_l, w1h, w1l, ph, ROWS, 4*DIM, DIM,   1.f, ffn_b1 + (long long)idx*4*DIM, nullptr, 0, 1, hh, hl);
        tcg_plain(hh,  hl,  w2h, w2l, pt, ROWS, DIM,   4*DIM, 1.f, ffn_b2 + (long long)idx*DIM,   nullptr, 0, 0, nullptr, nullptr);
        ln512_k<<<ROWS, 256>>>(pt, x, x, lg, lb, x_h, x_l);
    };

    for (int l = 0; l < NLAYER; l++) {
        const bf16* caw0h = w512h + (4 + (l*2+0)*4) * W;  const bf16* caw0l = w512l + (4 + (l*2+0)*4) * W;
        const bf16* caw1h = w512h + (4 + (l*2+1)*4) * W;  const bf16* caw1l = w512l + (4 + (l*2+1)*4) * W;
        const bf16* saw0h = w512h + (36 + (l*2+0)*4) * W; const bf16* saw0l = w512l + (36 + (l*2+0)*4) * W;
        const bf16* saw1h = w512h + (36 + (l*2+1)*4) * W; const bf16* saw1l = w512l + (36 + (l*2+1)*4) * W;
        const float* cab0 = ca_b + (long long)((l*2+0)*4) * DIM;
        const float* cab1 = ca_b + (long long)((l*2+1)*4) * DIM;
        const float* sab0 = sa_b + (long long)((l*2+0)*4) * DIM;
        const float* sab1 = sa_b + (long long)((l*2+1)*4) * DIM;
        const float* lg = ln_g + (long long)l * 6 * DIM;
        const float* lb = ln_b + (long long)l * 6 * DIM;

        mha(a, a_h, a_l, v_h, v_l, caw0h, caw0l, cab0, lg + 0*DIM, lb + 0*DIM);
        mha(v, v_h, v_l, a_h, a_l, caw1h, caw1l, cab1, lg + 3*DIM, lb + 3*DIM);
        mha(a, a_h, a_l, a_h, a_l, saw0h, saw0l, sab0, lg + 1*DIM, lb + 1*DIM);
        mha(v, v_h, v_l, v_h, v_l, saw1h, saw1l, sab1, lg + 4*DIM, lb + 4*DIM);
        ffn(a, a_h, a_l, l*2+0, lg + 2*DIM, lb + 2*DIM);
        ffn(v, v_h, v_l, l*2+1, lg + 5*DIM, lb + 5*DIM);
    }

    // ---- fused head ----
    tcg_plain(a_h, a_l, w512h + 2*W, w512l + 2*W, pq, ROWS, DIM, DIM, 1.f, nullptr, nullptr, 0, 0, nullptr, nullptr);
    tcg_plain(v_h, v_l, w512h + 3*W, w512l + 3*W, pq, ROWS, DIM, DIM, 1.f, out_b,   nullptr, 1, 0, nullptr, nullptr);
    ln512_k<<<ROWS, 256>>>(pq, nullptr, out, fln_g, fln_b, nullptr, nullptr);
}

// round 4
// speedup vs baseline: 4.1572x; 1.0404x over previous
#include <cuda_runtime.h>
#include <cuda_bf16.h>
#include <math.h>
#include <stdint.h>

#define NB 8
#define SEQ 256
#define DIM 512
#define NH 8
#define HDIM 64
#define NLAYER 4
#define ROWS (NB*SEQ)
#define NEGV -1e30f

typedef __nv_bfloat16 bf16;
typedef __nv_bfloat162 bf162;

// ---------------- static scratch (no allocation allowed) ----------------
__device__ float g_a  [ROWS*DIM];
__device__ float g_v  [ROWS*DIM];
__device__ float g_v2 [ROWS*DIM];
__device__ float g_q  [ROWS*DIM];
__device__ float g_k  [ROWS*DIM];
__device__ float g_vv [ROWS*DIM];
__device__ float g_ctx[ROWS*DIM];
__device__ float g_t  [ROWS*DIM];
__device__ float g_h  [ROWS*DIM*4];
__device__ float g_sc [NB*NH*SEQ*SEQ];
__device__ float g_sim[NB*SEQ*SEQ];

// bf16 hi/lo mirrors of activations (all row-major, same layout as fp32 source)
__device__ bf16 m_audh[ROWS*DIM],  m_audl[ROWS*DIM];
__device__ bf16 m_vidh[ROWS*256],  m_vidl[ROWS*256];
__device__ bf16 m_ah[ROWS*DIM],    m_al[ROWS*DIM];
__device__ bf16 m_vh[ROWS*DIM],    m_vl[ROWS*DIM];
__device__ bf16 m_v2h[ROWS*DIM],   m_v2l[ROWS*DIM];
__device__ bf16 m_qh[ROWS*DIM],    m_ql[ROWS*DIM];
__device__ bf16 m_kh[ROWS*DIM],    m_kl[ROWS*DIM];
__device__ bf16 m_vvh[ROWS*DIM],   m_vvl[ROWS*DIM];
__device__ bf16 m_ctxh[ROWS*DIM],  m_ctxl[ROWS*DIM];
__device__ bf16 m_hh[ROWS*DIM*4],  m_hl[ROWS*DIM*4];
__device__ bf16 m_sch[NB*NH*SEQ*SEQ], m_scl[NB*NH*SEQ*SEQ];
__device__ bf16 m_simh[NB*SEQ*SEQ],   m_siml[NB*SEQ*SEQ];

// bf16 hi/lo weights, NATIVE [K][N] layout (consumed via ldmatrix.trans)
__device__ bf16 c_aph[512*512],    c_apl[512*512];
__device__ bf16 c_vph[256*512],    c_vpl[256*512];
__device__ bf16 c_dtwh[512*512],   c_dtwl[512*512];
__device__ bf16 c_cah[32*512*512], c_cal[32*512*512];
__device__ bf16 c_sah[32*512*512], c_sal[32*512*512];
__device__ bf16 c_f1h[8*512*2048], c_f1l[8*512*2048];
__device__ bf16 c_f2h[8*2048*512], c_f2l[8*2048*512];
__device__ bf16 c_oh[1024*512],    c_ol[1024*512];

// ---------------- PTX helpers ----------------
__device__ __forceinline__ uint32_t smem_u32(const void* p) {
    return (uint32_t)__cvta_generic_to_shared(p);
}
__device__ __forceinline__ void cp16(uint32_t so, const void* g) {
    asm volatile("cp.async.cg.shared.global [%0], [%1], 16;" :: "r"(so), "l"(g));
}
__device__ __forceinline__ void ldm4(uint32_t* r, uint32_t addr) {
    asm volatile("ldmatrix.sync.aligned.m8n8.x4.shared.b16 {%0,%1,%2,%3}, [%4];"
        : "=r"(r[0]), "=r"(r[1]), "=r"(r[2]), "=r"(r[3]) : "r"(addr));
}
__device__ __forceinline__ void ldm4t(uint32_t* r, uint32_t addr) {
    asm volatile("ldmatrix.sync.aligned.m8n8.x4.trans.shared.b16 {%0,%1,%2,%3}, [%4];"
        : "=r"(r[0]), "=r"(r[1]), "=r"(r[2]), "=r"(r[3]) : "r"(addr));
}
__device__ __forceinline__ void mma16816(float* d, const uint32_t* a, const uint32_t* b) {
    asm volatile(
        "mma.sync.aligned.m16n8k16.row.col.f32.bf16.bf16.f32 "
        "{%0,%1,%2,%3}, {%4,%5,%6,%7}, {%8,%9}, {%0,%1,%2,%3};"
        : "+f"(d[0]), "+f"(d[1]), "+f"(d[2]), "+f"(d[3])
        : "r"(a[0]), "r"(a[1]), "r"(a[2]), "r"(a[3]), "r"(b[0]), "r"(b[1]));
}

// ---------------- HMMA GEMM ----------------
// C = act(alpha*(Ah+Al)@B + bias(+bias2) + beta*C + rscale*resid), acc = Ah*Bh + Ah*Bl + Al*Bh.
// A: [M][K] row-major bf16 hi/lo.
// B: TRB=false -> [N][K] K-major; TRB=true -> [K][N] row-major (ldmatrix.trans).
template<int BM, int BN, int NWM, int NWN, bool TRB>
__global__ void __launch_bounds__(NWM*NWN*32)
mma_gemm(const bf16* __restrict__ Ah_, const bf16* __restrict__ Al_,
         const bf16* __restrict__ Bh_, const bf16* __restrict__ Bl_,
         float* __restrict__ C,
         int K, int lda, int ldb, int ldc,
         long long sAo, long long sAi, long long sBo, long long sBi,
         long long sCo, long long sCi, int inner,
         float alpha, const float* __restrict__ bias, const float* __restrict__ bias2,
         const float* __restrict__ resid, float rscale, int beta, int act,
         bf16* outh, bf16* outl)
{
    constexpr int TH = NWM * NWN * 32;
    constexpr int WN = BN / NWN;
    constexpr int NF = WN / 8;
    constexpr int ACH = BM * 4;             // 16B chunks per A array per stage
    constexpr int BCH = BN * 4;             // same count either layout
    constexpr int CPR = BN / 8;             // chunks per k-row (TRB)
    constexpr int STAGE = (BM + BN) * 128;  // bytes per stage

    extern __shared__ char smem[];
    uint32_t sb = smem_u32(smem);

    int z = blockIdx.z, zo = z / inner, zi = z - zo * inner;
    long long aoff = zo * sAo + zi * sAi;
    long long boff = zo * sBo + zi * sBi;
    Ah_ += aoff; Al_ += aoff;
    Bh_ += boff; Bl_ += boff;
    long long coff = zo * sCo + zi * sCi;
    C += coff;
    if (resid) resid += coff;
    if (outh) { outh += coff; outl += coff; }

    int tid = threadIdx.x, wid = tid >> 5, lane = tid & 31;
    int wm = wid % NWM, wn = wid / NWM;
    int row0 = blockIdx.y * BM, col0 = blockIdx.x * BN;

    auto loadStage = [&](int k0, int st) {
        uint32_t sbase = sb + st * STAGE;
#pragma unroll
        for (int idx = tid; idx < ACH; idx += TH) {
            int r = idx >> 2, c = idx & 3;
            int cs = c ^ ((r >> 1) & 3);
            uint32_t so = sbase + (uint32_t)(r * 4 + cs) * 16;
            long long g = (long long)(row0 + r) * lda + k0 + c * 8;
            cp16(so,           Ah_ + g);
            cp16(so + BM * 64, Al_ + g);
        }
        if (!TRB) {
#pragma unroll
            for (int idx = tid; idx < BCH; idx += TH) {
                int r = idx >> 2, c = idx & 3;
                int cs = c ^ ((r >> 1) & 3);
                uint32_t so = sbase + BM * 128 + (uint32_t)(r * 4 + cs) * 16;
                long long g = (long long)(col0 + r) * ldb + k0 + c * 8;
                cp16(so,           Bh_ + g);
                cp16(so + BN * 64, Bl_ + g);
            }
        } else {
#pragma unroll
            for (int idx = tid; idx < BCH; idx += TH) {
                int r = idx / CPR, c = idx % CPR;
                int cs = c ^ (r & 7);
                uint32_t so = sbase + BM * 128 + (uint32_t)(r * CPR + cs) * 16;
                long long g = (long long)(k0 + r) * ldb + col0 + c * 8;
                cp16(so,           Bh_ + g);
                cp16(so + BN * 64, Bl_ + g);
            }
        }
        asm volatile("cp.async.commit_group;");
    };

    float acc[2][NF][4];
#pragma unroll
    for (int i = 0; i < 2; i++)
#pragma unroll
        for (int j = 0; j < NF; j++)
#pragma unroll
            for (int q = 0; q < 4; q++) acc[i][j][q] = 0.f;

    int nch = K / 32;
    loadStage(0, 0);
    if (nch > 1) loadStage(32, 1);

    for (int s = 0; s < nch; s++) {
        __syncthreads();   // everyone done reading the stage we are about to overwrite
        if (s + 2 < nch) {
            loadStage((s + 2) * 32, (s + 2) % 3);
            asm volatile("cp.async.wait_group 2;");
        } else if (s + 1 < nch) {
            asm volatile("cp.async.wait_group 1;");
        } else {
            asm volatile("cp.async.wait_group 0;");
        }
        __syncthreads();   // stage s visible to all
        uint32_t sbase = sb + (s % 3) * STAGE;
#pragma unroll
        for (int ks = 0; ks < 2; ks++) {
            uint32_t ah[2][4], al[2][4];
#pragma unroll
            for (int mf = 0; mf < 2; mf++) {
                int row = wm * 32 + mf * 16 + (lane & 15);
                int c = ks * 2 + (lane >> 4);
                int cs = c ^ ((row >> 1) & 3);
                uint32_t ad = sbase + (uint32_t)(row * 4 + cs) * 16;
                ldm4(ah[mf], ad);
                ldm4(al[mf], ad + BM * 64);
            }
            uint32_t bh[NF][2], bl[NF][2];
            if (!TRB) {
#pragma unroll
                for (int nf = 0; nf < NF; nf += 2) {
                    int rown = wn * WN + nf * 8 + (lane >> 4) * 8 + (lane & 7);
                    int c = ks * 2 + ((lane >> 3) & 1);
                    int cs = c ^ ((rown >> 1) & 3);
                    uint32_t bd = sbase + BM * 128 + (uint32_t)(rown * 4 + cs) * 16;
                    uint32_t t[4];
                    ldm4(t, bd);
                    bh[nf][0] = t[0]; bh[nf][1] = t[1]; bh[nf+1][0] = t[2]; bh[nf+1][1] = t[3];
                    ldm4(t, bd + BN * 64);
                    bl[nf][0] = t[0]; bl[nf][1] = t[1]; bl[nf+1][0] = t[2]; bl[nf+1][1] = t[3];
                }
            } else {
#pragma unroll
                for (int nf = 0; nf < NF; nf += 2) {
                    int n0 = wn * WN + nf * 8;
                    int k = ks * 16 + (lane & 7) + ((lane >> 3) & 1) * 8;
                    int c = (n0 >> 3) + (lane >> 4);
                    int cs = c ^ (k & 7);
                    uint32_t bd = sbase + BM * 128 + (uint32_t)(k * CPR + cs) * 16;
                    uint32_t t[4];
                    ldm4t(t, bd);
                    bh[nf][0] = t[0]; bh[nf][1] = t[1]; bh[nf+1][0] = t[2]; bh[nf+1][1] = t[3];
                    ldm4t(t, bd + BN * 64);
                    bl[nf][0] = t[0]; bl[nf][1] = t[1]; bl[nf+1][0] = t[2]; bl[nf+1][1] = t[3];
                }
            }
#pragma unroll
            for (int mf = 0; mf < 2; mf++)
#pragma unroll
                for (int nf = 0; nf < NF; nf++) {
                    mma16816(acc[mf][nf], ah[mf], bh[nf]);
                    mma16816(acc[mf][nf], ah[mf], bl[nf]);
                    mma16816(acc[mf][nf], al[mf], bh[nf]);
                }
        }
    }

    // ---- epilogue ----
    auto epi2 = [&](int r, int c, float v0, float v1) {
        long long off = (long long)r * ldc + c;
        v0 *= alpha; v1 *= alpha;
        if (bias)  { float2 b2 = *(const float2*)&bias[c];  v0 += b2.x; v1 += b2.y; }
        if (bias2) { float2 b2 = *(const float2*)&bias2[c]; v0 += b2.x; v1 += b2.y; }
        if (beta)  { float2 c2 = *(const float2*)&C[off];   v0 += c2.x; v1 += c2.y; }
        if (resid) { float2 r2 = *(const float2*)&resid[off]; v0 += rscale * r2.x; v1 += rscale * r2.y; }
        if (act) {
            v0 = 0.5f * v0 * (1.f + erff(v0 * 0.70710678118654752f));
            v1 = 0.5f * v1 * (1.f + erff(v1 * 0.70710678118654752f));
        }
        *(float2*)&C[off] = make_float2(v0, v1);
        if (outh) {
            bf16 h0 = __float2bfloat16(v0), h1 = __float2bfloat16(v1);
            *(bf162*)&outh[off] = bf162(h0, h1);
            *(bf162*)&outl[off] = bf162(__float2bfloat16(v0 - __bfloat162float(h0)),
                                        __float2bfloat16(v1 - __bfloat162float(h1)));
        }
    };
#pragma unroll
    for (int mf = 0; mf < 2; mf++) {
        int r0 = row0 + wm * 32 + mf * 16 + (lane >> 2);
#pragma unroll
        for (int nf = 0; nf < NF; nf++) {
            int c = col0 + wn * WN + nf * 8 + (lane & 3) * 2;
            epi2(r0,     c, acc[mf][nf][0], acc[mf][nf][1]);
            epi2(r0 + 8, c, acc[mf][nf][2], acc[mf][nf][3]);
        }
    }
}

// ---------------- vectorized fp32 -> bf16 hi/lo convert ----------------
__global__ void cvt4_k(const float* __restrict__ x, bf16* __restrict__ h, bf16* __restrict__ l, int n)
{
    int i = (blockIdx.x * 256 + threadIdx.x) * 4;
    if (i >= n) return;
    float4 v = *(const float4*)(x + i);
    bf16 h0 = __float2bfloat16(v.x), h1 = __float2bfloat16(v.y);
    bf16 h2 = __float2bfloat16(v.z), h3 = __float2bfloat16(v.w);
    *(bf162*)(h + i)     = bf162(h0, h1);
    *(bf162*)(h + i + 2) = bf162(h2, h3);
    *(bf162*)(l + i)     = bf162(__float2bfloat16(v.x - __bfloat162float(h0)),
                                 __float2bfloat16(v.y - __bfloat162float(h1)));
    *(bf162*)(l + i + 2) = bf162(__float2bfloat16(v.z - __bfloat162float(h2)),
                                 __float2bfloat16(v.w - __bfloat162float(h3)));
}

// ---------------- softmax over 256-wide rows -> bf16 hi/lo mirrors ----------------
__global__ void softmax256_k(const float* __restrict__ x, bf16* __restrict__ oh, bf16* __restrict__ ol)
{
    __shared__ float red[8];
    __shared__ float bc[2];
    int t = threadIdx.x;
    const float* p = x + (long long)blockIdx.x * 256;
    float v = p[t];
    float m = v;
#pragma unroll
    for (int o = 16; o; o >>= 1) m = fmaxf(m, __shfl_xor_sync(0xffffffffu, m, o));
    if ((t & 31) == 0) red[t >> 5] = m;
    __syncthreads();
    if (t == 0) { float mm = red[0]; for (int i = 1; i < 8; i++) mm = fmaxf(mm, red[i]); bc[0] = mm; }
    __syncthreads();
    float e = expf(v - bc[0]);
    float s = e;
#pragma unroll
    for (int o = 16; o; o >>= 1) s += __shfl_xor_sync(0xffffffffu, s, o);
    if ((t & 31) == 0) red[t >> 5] = s;
    __syncthreads();
    if (t == 0) { float tt = 0.f; for (int i = 0; i < 8; i++) tt += red[i]; bc[1] = 1.f / tt; }
    __syncthreads();
    float val = e * bc[1];
    long long o = (long long)blockIdx.x * 256 + t;
    bf16 hh = __float2bfloat16(val);
    oh[o] = hh;
    ol[o] = __float2bfloat16(val - __bfloat162float(hh));
}

// ---------------- LayerNorm 512 wide: y = LN(x (+ r)) * g + b, optional bf16 mirrors ----------------
__global__ void ln512_k(const float* __restrict__ x, const float* r,
                        float* y, const float* __restrict__ g, const float* __restrict__ bb,
                        bf16* oh, bf16* ol)
{
    __shared__ float red[8];
    __shared__ float bc;
    long long row = blockIdx.x;
    int t = threadIdx.x;
    const float* px = x + row * 512;
    float v0 = px[t], v1 = px[t + 256];
    if (r) { const float* pr = r + row * 512; v0 += pr[t]; v1 += pr[t + 256]; }
    float s = v0 + v1;
#pragma unroll
    for (int o = 16; o; o >>= 1) s += __shfl_xor_sync(0xffffffffu, s, o);
    if ((t & 31) == 0) red[t >> 5] = s;
    __syncthreads();
    if (t == 0) { float tt = 0.f; for (int i = 0; i < 8; i++) tt += red[i]; bc = tt * (1.f / 512.f); }
    __syncthreads();
    float mean = bc;
    float d0 = v0 - mean, d1 = v1 - mean;
    float q = d0 * d0 + d1 * d1;
#pragma unroll
    for (int o = 16; o; o >>= 1) q += __shfl_xor_sync(0xffffffffu, q, o);
    if ((t & 31) == 0) red[t >> 5] = q;
    __syncthreads();
    if (t == 0) { float tt = 0.f; for (int i = 0; i < 8; i++) tt += red[i]; bc = tt * (1.f / 512.f); }
    __syncthreads();
    float inv = rsqrtf(bc + 1e-5f);
    float y0 = d0 * inv * g[t]       + bb[t];
    float y1 = d1 * inv * g[t + 256] + bb[t + 256];
    float* py = y + row * 512;
    py[t] = y0;  py[t + 256] = y1;
    if (oh) {
        bf16 h0 = __float2bfloat16(y0), h1 = __float2bfloat16(y1);
        oh[row * 512 + t] = h0;       ol[row * 512 + t] = __float2bfloat16(y0 - __bfloat162float(h0));
        oh[row * 512 + t + 256] = h1; ol[row * 512 + t + 256] = __float2bfloat16(y1 - __bfloat162float(h1));
    }
}

// ---------------- L2 normalize 512-wide, writes fp32 in place + bf16 mirrors ----------------
__global__ void l2n_k(float* x, bf16* oh, bf16* ol)
{
    __shared__ float red[8];
    __shared__ float bc;
    long long row = blockIdx.x;
    int t = threadIdx.x;
    float* p = x + row * 512;
    float v0 = p[t], v1 = p[t + 256];
    float q = v0 * v0 + v1 * v1;
#pragma unroll
    for (int o = 16; o; o >>= 1) q += __shfl_xor_sync(0xffffffffu, q, o);
    if ((t & 31) == 0) red[t >> 5] = q;
    __syncthreads();
    if (t == 0) { float tt = 0.f; for (int i = 0; i < 8; i++) tt += red[i];
                  bc = 1.f / fmaxf(sqrtf(tt), 1e-12f); }
    __syncthreads();
    v0 *= bc; v1 *= bc;
    p[t] = v0; p[t + 256] = v1;
    bf16 h0 = __float2bfloat16(v0), h1 = __float2bfloat16(v1);
    oh[row * 512 + t] = h0;       ol[row * 512 + t] = __float2bfloat16(v0 - __bfloat162float(h0));
    oh[row * 512 + t + 256] = h1; ol[row * 512 + t + 256] = __float2bfloat16(v1 - __bfloat162float(h1));
}

// ---------------- DTW wavefront DP ----------------
__global__ void dtw_k(const float* __restrict__ sim, float* score)
{
    __shared__ float buf[3][SEQ + 1];
    int b = blockIdx.x;
    const float* S = sim + (long long)b * SEQ * SEQ;
    int t = threadIdx.x;
    float *dm2 = buf[0], *dm1 = buf[1], *dc = buf[2];
    if (t == 0) { buf[0][0] = 0.f; buf[1][0] = NEGV; buf[1][1] = NEGV; }
    __syncthreads();
    for (int td = 2; td <= 2 * SEQ; td++) {
        int i = t + 1;
        int j = td - i;
        float val = 0.f;
        bool active = (j >= 1 && j <= SEQ);
        if (active) {
            float dg = dm2[i - 1];
            float up = dm1[i - 1];
            float lf = dm1[i];
            val = S[(i - 1) * SEQ + (j - 1)] + fmaxf(dg, fmaxf(up, lf));
            dc[i] = val;
        }
        if (t == 0 && td <= SEQ) { dc[0] = NEGV; dc[td] = NEGV; }
        if (td == 2 * SEQ && i == SEQ) score[b] = val;
        __syncthreads();
        float* tmp = dm2; dm2 = dm1; dm1 = dc; dc = tmp;
    }
}

// ---------------- host-side launch helper ----------------
template<bool TRB>
static void tcgT(const bf16* Ah, const bf16* Al, const bf16* Bh, const bf16* Bl,
                 float* C, int M, int N, int K, int lda, int ldb, int ldc,
                 long long sAo, long long sAi, long long sBo, long long sBi,
                 long long sCo, long long sCi, int inner, int batch,
                 float alpha, const float* bias, const float* bias2,
                 const float* resid, float rs, int beta, int act,
                 bf16* outh, bf16* outl)
{
    if (N % 128 == 0) {
        long long c128 = (long long)(M / 128) * (N / 128) * batch;
        if (M % 128 == 0 && c128 >= 120) {
            constexpr int SM = 3 * (128 + 128) * 128;
            cudaFuncSetAttribute(mma_gemm<128,128,4,2,TRB>, cudaFuncAttributeMaxDynamicSharedMemorySize, SM);
            mma_gemm<128,128,4,2,TRB><<<dim3(N/128, M/128, batch), 256, SM>>>(
                Ah, Al, Bh, Bl, C, K, lda, ldb, ldc,
                sAo, sAi, sBo, sBi, sCo, sCi, inner, alpha, bias, bias2, resid, rs, beta, act, outh, outl);
        } else {
            constexpr int SM = 3 * (64 + 128) * 128;
            cudaFuncSetAttribute(mma_gemm<64,128,2,2,TRB>, cudaFuncAttributeMaxDynamicSharedMemorySize, SM);
            mma_gemm<64,128,2,2,TRB><<<dim3(N/128, M/64, batch), 128, SM>>>(
                Ah, Al, Bh, Bl, C, K, lda, ldb, ldc,
                sAo, sAi, sBo, sBi, sCo, sCi, inner, alpha, bias, bias2, resid, rs, beta, act, outh, outl);
        }
    } else {
        constexpr int SM = 3 * (128 + 64) * 128;
        cudaFuncSetAttribute(mma_gemm<128,64,4,2,TRB>, cudaFuncAttributeMaxDynamicSharedMemorySize, SM);
        mma_gemm<128,64,4,2,TRB><<<dim3(N/64, M/128, batch), 256, SM>>>(
            Ah, Al, Bh, Bl, C, K, lda, ldb, ldc,
            sAo, sAi, sBo, sBi, sCo, sCi, inner, alpha, bias, bias2, resid, rs, beta, act, outh, outl);
    }
}

// weight GEMM: B in native [K][N], ldb = N
static void wgemm(const bf16* Ah, const bf16* Al, const bf16* Bh, const bf16* Bl,
                  float* C, int M, int N, int K,
                  float alpha, const float* bias, const float* bias2, int beta, int act,
                  bf16* outh, bf16* outl)
{
    tcgT<true>(Ah, Al, Bh, Bl, C, M, N, K, K, N, N, 0, 0, 0, 0, 0, 0, 1, 1,
               alpha, bias, bias2, nullptr, 0.f, beta, act, outh, outl);
}

extern "C" void kernel_launch(void* const* d_in, const int* in_sizes, int n_in,
                              void* d_out, int out_size)
{
    const float* audio  = (const float*)d_in[0];
    const float* video  = (const float*)d_in[1];
    const float* ap_w   = (const float*)d_in[2];
    const float* ap_b   = (const float*)d_in[3];
    const float* vp_w   = (const float*)d_in[4];
    const float* vp_b   = (const float*)d_in[5];
    const float* dtw_w  = (const float*)d_in[6];
    const float* dtw_b  = (const float*)d_in[7];
    const float* mod_emb= (const float*)d_in[8];
    const float* ca_w   = (const float*)d_in[9];
    const float* ca_b   = (const float*)d_in[10];
    const float* sa_w   = (const float*)d_in[11];
    const float* sa_b   = (const float*)d_in[12];
    const float* ln_g   = (const float*)d_in[13];
    const float* ln_b   = (const float*)d_in[14];
    const float* ffn_w1 = (const float*)d_in[15];
    const float* ffn_b1 = (const float*)d_in[16];
    const float* ffn_w2 = (const float*)d_in[17];
    const float* ffn_b2 = (const float*)d_in[18];
    const float* out_w  = (const float*)d_in[19];
    const float* out_b  = (const float*)d_in[20];
    const float* fln_g  = (const float*)d_in[21];
    const float* fln_b  = (const float*)d_in[22];

    float *pa,*pv,*pv2,*pq,*pk,*pvv,*pctx,*pt,*ph,*psc,*psim;
    cudaGetSymbolAddress((void**)&pa,  g_a);
    cudaGetSymbolAddress((void**)&pv,  g_v);
    cudaGetSymbolAddress((void**)&pv2, g_v2);
    cudaGetSymbolAddress((void**)&pq,  g_q);
    cudaGetSymbolAddress((void**)&pk,  g_k);
    cudaGetSymbolAddress((void**)&pvv, g_vv);
    cudaGetSymbolAddress((void**)&pctx,g_ctx);
    cudaGetSymbolAddress((void**)&pt,  g_t);
    cudaGetSymbolAddress((void**)&ph,  g_h);
    cudaGetSymbolAddress((void**)&psc, g_sc);
    cudaGetSymbolAddress((void**)&psim,g_sim);

    bf16 *audh,*audl,*vidh,*vidl,*ah,*al,*vh,*vl,*v2h,*v2l,*qh,*ql,*kh,*kl;
    bf16 *vvh,*vvl,*ctxh,*ctxl,*hh,*hl,*sch,*scl,*simh,*siml;
    bf16 *aph,*apl,*vph,*vpl,*dtwh,*dtwl,*cah,*cal,*sah,*sal,*f1h,*f1l,*f2h,*f2l,*owh,*owl;
    cudaGetSymbolAddress((void**)&audh, m_audh); cudaGetSymbolAddress((void**)&audl, m_audl);
    cudaGetSymbolAddress((void**)&vidh, m_vidh); cudaGetSymbolAddress((void**)&vidl, m_vidl);
    cudaGetSymbolAddress((void**)&ah, m_ah);     cudaGetSymbolAddress((void**)&al, m_al);
    cudaGetSymbolAddress((void**)&vh, m_vh);     cudaGetSymbolAddress((void**)&vl, m_vl);
    cudaGetSymbolAddress((void**)&v2h, m_v2h);   cudaGetSymbolAddress((void**)&v2l, m_v2l);
    cudaGetSymbolAddress((void**)&qh, m_qh);     cudaGetSymbolAddress((void**)&ql, m_ql);
    cudaGetSymbolAddress((void**)&kh, m_kh);     cudaGetSymbolAddress((void**)&kl, m_kl);
    cudaGetSymbolAddress((void**)&vvh, m_vvh);   cudaGetSymbolAddress((void**)&vvl, m_vvl);
    cudaGetSymbolAddress((void**)&ctxh, m_ctxh); cudaGetSymbolAddress((void**)&ctxl, m_ctxl);
    cudaGetSymbolAddress((void**)&hh, m_hh);     cudaGetSymbolAddress((void**)&hl, m_hl);
    cudaGetSymbolAddress((void**)&sch, m_sch);   cudaGetSymbolAddress((void**)&scl, m_scl);
    cudaGetSymbolAddress((void**)&simh, m_simh); cudaGetSymbolAddress((void**)&siml, m_siml);
    cudaGetSymbolAddress((void**)&aph, c_aph);   cudaGetSymbolAddress((void**)&apl, c_apl);
    cudaGetSymbolAddress((void**)&vph, c_vph);   cudaGetSymbolAddress((void**)&vpl, c_vpl);
    cudaGetSymbolAddress((void**)&dtwh, c_dtwh); cudaGetSymbolAddress((void**)&dtwl, c_dtwl);
    cudaGetSymbolAddress((void**)&cah, c_cah);   cudaGetSymbolAddress((void**)&cal, c_cal);
    cudaGetSymbolAddress((void**)&sah, c_sah);   cudaGetSymbolAddress((void**)&sal, c_sal);
    cudaGetSymbolAddress((void**)&f1h, c_f1h);   cudaGetSymbolAddress((void**)&f1l, c_f1l);
    cudaGetSymbolAddress((void**)&f2h, c_f2h);   cudaGetSymbolAddress((void**)&f2l, c_f2l);
    cudaGetSymbolAddress((void**)&owh, c_oh);    cudaGetSymbolAddress((void**)&owl, c_ol);

    float* out = (float*)d_out;
    float* out_score = out + (out_size - NB);

    const long long SD = (long long)SEQ * DIM;
    const long long SS = (long long)SEQ * SEQ;
    const long long W  = (long long)DIM * DIM;

    auto cv = [&](const float* x, bf16* h, bf16* l, long long n) {
        cvt4_k<<<(int)((n / 4 + 255) / 256), 256>>>(x, h, l, (int)n);
    };

    // ---- weight + input converts (pure streaming, no transpose) ----
    cv(ap_w,  aph, apl, 512*512);
    cv(vp_w,  vph, vpl, 256*512);
    cv(dtw_w, dtwh, dtwl, 512*512);
    cv(ca_w,  cah, cal, 32ll*512*512);
    cv(sa_w,  sah, sal, 32ll*512*512);
    cv(ffn_w1, f1h, f1l, 8ll*512*2048);
    cv(ffn_w2, f2h, f2l, 8ll*2048*512);
    cv(out_w, owh, owl, 1024*512);
    cv(audio, audh, audl, (long long)ROWS*DIM);
    cv(video, vidh, vidl, (long long)ROWS*256);

    // ---- projections + modality embeddings ----
    wgemm(audh, audl, aph, apl, pa, ROWS, DIM, DIM, 1.f, ap_b, mod_emb,       0, 0, ah, al);
    wgemm(vidh, vidl, vph, vpl, pv, ROWS, DIM, 256, 1.f, vp_b, mod_emb + DIM, 0, 0, vh, vl);

    // ---- DTW similarity ----
    wgemm(ah, al, dtwh, dtwl, pq, ROWS, DIM, DIM, 1.f, dtw_b, nullptr, 0, 0, nullptr, nullptr);
    wgemm(vh, vl, dtwh, dtwl, pk, ROWS, DIM, DIM, 1.f, dtw_b, nullptr, 0, 0, nullptr, nullptr);
    l2n_k<<<ROWS, 256>>>(pq, qh, ql);
    l2n_k<<<ROWS, 256>>>(pk, kh, kl);
    // sim[b] = an[b] @ vn[b]^T   (B K-major)
    tcgT<false>(qh, ql, kh, kl, psim, SEQ, SEQ, DIM, DIM, DIM, SEQ,
                SD, 0, SD, 0, SS, 0, 1, NB,
                1.f, nullptr, nullptr, nullptr, 0.f, 0, 0, nullptr, nullptr);
    dtw_k<<<NB, 256>>>(psim, out_score);
    softmax256_k<<<NB*SEQ, 256>>>(psim, simh, siml);
    // v2 = 0.5*v + 0.5*softmax(sim) @ v   (B = v row-major [k][n], TRB)
    tcgT<true>(simh, siml, vh, vl, pv2, SEQ, DIM, SEQ, SEQ, DIM, DIM,
               SS, 0, SD, 0, SD, 0, 1, NB,
               0.5f, nullptr, nullptr, pv, 0.5f, 0, 0, v2h, v2l);

    float* a = pa;
    float* v = pv2;
    bf16 *a_h = ah, *a_l = al, *v_h = v2h, *v_l = v2l;

    auto mha = [&](float* x, bf16* x_h, bf16* x_l, bf16* kv_h, bf16* kv_l,
                   const bf16* Wh, const bf16* Wl, const float* bb,
                   const float* lg, const float* lb) {
        wgemm(x_h,  x_l,  Wh + 0*W, Wl + 0*W, pq,  ROWS, DIM, DIM, 1.f, bb,         nullptr, 0, 0, qh, ql);
        wgemm(kv_h, kv_l, Wh + 1*W, Wl + 1*W, pk,  ROWS, DIM, DIM, 1.f, bb + DIM,   nullptr, 0, 0, kh, kl);
        wgemm(kv_h, kv_l, Wh + 2*W, Wl + 2*W, pvv, ROWS, DIM, DIM, 1.f, bb + 2*DIM, nullptr, 0, 0, vvh, vvl);
        // scores[b,h] = (1/8) Q_bh @ K_bh^T   (B K-major)
        tcgT<false>(qh, ql, kh, kl, psc, SEQ, SEQ, HDIM, DIM, DIM, SEQ,
                    SD, HDIM, SD, HDIM, (long long)NH*SS, SS, NH, NB*NH,
                    0.125f, nullptr, nullptr, nullptr, 0.f, 0, 0, nullptr, nullptr);
        softmax256_k<<<NB*NH*SEQ, 256>>>(psc, sch, scl);
        // ctx[b,h] = P @ V_bh   (B = vv row-major [k=seq][n], head slice via col offset, TRB)
        tcgT<true>(sch, scl, vvh, vvl, pctx, SEQ, HDIM, SEQ, SEQ, DIM, DIM,
                   (long long)NH*SS, SS, SD, HDIM, SD, HDIM, NH, NB*NH,
                   1.f, nullptr, nullptr, nullptr, 0.f, 0, 0, ctxh, ctxl);
        wgemm(ctxh, ctxl, Wh + 3*W, Wl + 3*W, pt, ROWS, DIM, DIM, 1.f, bb + 3*DIM, nullptr, 0, 0, nullptr, nullptr);
        ln512_k<<<ROWS, 256>>>(pt, x, x, lg, lb, x_h, x_l);
    };

    auto ffn = [&](float* x, bf16* x_h, bf16* x_l, int idx,
                   const float* lg, const float* lb) {
        const bf16* w1h = f1h + (long long)idx * 512 * 2048;
        const bf16* w1l = f1l + (long long)idx * 512 * 2048;
        const bf16* w2h = f2h + (long long)idx * 2048 * 512;
        const bf16* w2l = f2l + (long long)idx * 2048 * 512;
        wgemm(x_h, x_l, w1h, w1l, ph, ROWS, 4*DIM, DIM,   1.f, ffn_b1 + (long long)idx*4*DIM, nullptr, 0, 1, hh, hl);
        wgemm(hh,  hl,  w2h, w2l, pt, ROWS, DIM,   4*DIM, 1.f, ffn_b2 + (long long)idx*DIM,   nullptr, 0, 0, nullptr, nullptr);
        ln512_k<<<ROWS, 256>>>(pt, x, x, lg, lb, x_h, x_l);
    };

    for (int l = 0; l < NLAYER; l++) {
        const bf16* caw0h = cah + (long long)((l*2+0)*4) * W;  const bf16* caw0l = cal + (long long)((l*2+0)*4) * W;
        const bf16* caw1h = cah + (long long)((l*2+1)*4) * W;  const bf16* caw1l = cal + (long long)((l*2+1)*4) * W;
        const bf16* saw0h = sah + (long long)((l*2+0)*4) * W;  const bf16* saw0l = sal + (long long)((l*2+0)*4) * W;
        const bf16* saw1h = sah + (long long)((l*2+1)*4) * W;  const bf16* saw1l = sal + (long long)((l*2+1)*4) * W;
        const float* cab0 = ca_b + (long long)((l*2+0)*4) * DIM;
        const float* cab1 = ca_b + (long long)((l*2+1)*4) * DIM;
        const float* sab0 = sa_b + (long long)((l*2+0)*4) * DIM;
        const float* sab1 = sa_b + (long long)((l*2+1)*4) * DIM;
        const float* lg = ln_g + (long long)l * 6 * DIM;
        const float* lb = ln_b + (long long)l * 6 * DIM;

        mha(a, a_h, a_l, v_h, v_l, caw0h, caw0l, cab0, lg + 0*DIM, lb + 0*DIM);
        mha(v, v_h, v_l, a_h, a_l, caw1h, caw1l, cab1, lg + 3*DIM, lb + 3*DIM);
        mha(a, a_h, a_l, a_h, a_l, saw0h, saw0l, sab0, lg + 1*DIM, lb + 1*DIM);
        mha(v, v_h, v_l, v_h, v_l, saw1h, saw1l, sab1, lg + 4*DIM, lb + 4*DIM);
        ffn(a, a_h, a_l, l*2+0, lg + 2*DIM, lb + 2*DIM);
        ffn(v, v_h, v_l, l*2+1, lg + 5*DIM, lb + 5*DIM);
    }

    // ---- fused head: [a | v] @ out_w + out_b, then LN -> d_out ----
    wgemm(a_h, a_l, owh,             owl,             pq, ROWS, DIM, DIM, 1.f, nullptr, nullptr, 0, 0, nullptr, nullptr);
    wgemm(v_h, v_l, owh + 512*512,   owl + 512*512,   pq, ROWS, DIM, DIM, 1.f, out_b,   nullptr, 1, 0, nullptr, nullptr);
    ln512_k<<<ROWS, 256>>>(pq, nullptr, out, fln_g, fln_b, nullptr, nullptr);
}

// round 5
// speedup vs baseline: 5.0219x; 1.2080x over previous
#include <cuda_runtime.h>
#include <cuda_bf16.h>
#include <math.h>
#include <stdint.h>

#define NB 8
#define SEQ 256
#define DIM 512
#define NH 8
#define HDIM 64
#define NLAYER 4
#define ROWS (NB*SEQ)
#define NEGV -1e30f

typedef __nv_bfloat16 bf16;
typedef __nv_bfloat162 bf162;

// ---------------- static scratch (no allocation allowed) ----------------
__device__ float g_a  [ROWS*DIM];
__device__ float g_v  [ROWS*DIM];
__device__ float g_v2 [ROWS*DIM];
__device__ float g_q  [ROWS*DIM];
__device__ float g_k  [ROWS*DIM];
__device__ float g_t  [ROWS*DIM];
__device__ float g_sc [NB*NH*SEQ*SEQ];
__device__ float g_sim[NB*SEQ*SEQ];

// bf16 hi/lo mirrors of activations (row-major, same layout as fp32 source)
__device__ bf16 m_audh[ROWS*DIM],  m_audl[ROWS*DIM];
__device__ bf16 m_vidh[ROWS*256],  m_vidl[ROWS*256];
__device__ bf16 m_ah[ROWS*DIM],    m_al[ROWS*DIM];
__device__ bf16 m_vh[ROWS*DIM],    m_vl[ROWS*DIM];
__device__ bf16 m_v2h[ROWS*DIM],   m_v2l[ROWS*DIM];
__device__ bf16 m_qh[ROWS*DIM],    m_ql[ROWS*DIM];
__device__ bf16 m_kh[ROWS*DIM],    m_kl[ROWS*DIM];
__device__ bf16 m_qkvh[3*ROWS*DIM],m_qkvl[3*ROWS*DIM];
__device__ bf16 m_ctxh[ROWS*DIM],  m_ctxl[ROWS*DIM];
__device__ bf16 m_hh[ROWS*DIM*4],  m_hl[ROWS*DIM*4];
__device__ bf16 m_sch[NB*NH*SEQ*SEQ], m_scl[NB*NH*SEQ*SEQ];
__device__ bf16 m_simh[NB*SEQ*SEQ],   m_siml[NB*SEQ*SEQ];
__device__ bf16 m_cath[ROWS*1024],    m_catl[ROWS*1024];

// bf16 hi/lo weights, NATIVE [K][N] layout (consumed via ldmatrix.trans)
__device__ bf16 c_aph[512*512],    c_apl[512*512];
__device__ bf16 c_vph[256*512],    c_vpl[256*512];
__device__ bf16 c_dtwh[512*512],   c_dtwl[512*512];
__device__ bf16 c_cah[32*512*512], c_cal[32*512*512];
__device__ bf16 c_sah[32*512*512], c_sal[32*512*512];
__device__ bf16 c_f1h[8*512*2048], c_f1l[8*512*2048];
__device__ bf16 c_f2h[8*2048*512], c_f2l[8*2048*512];
__device__ bf16 c_oh[1024*512],    c_ol[1024*512];

// ---------------- PTX helpers ----------------
__device__ __forceinline__ uint32_t smem_u32(const void* p) {
    return (uint32_t)__cvta_generic_to_shared(p);
}
__device__ __forceinline__ void cp16(uint32_t so, const void* g) {
    asm volatile("cp.async.cg.shared.global [%0], [%1], 16;" :: "r"(so), "l"(g));
}
__device__ __forceinline__ void ldm4(uint32_t* r, uint32_t addr) {
    asm volatile("ldmatrix.sync.aligned.m8n8.x4.shared.b16 {%0,%1,%2,%3}, [%4];"
        : "=r"(r[0]), "=r"(r[1]), "=r"(r[2]), "=r"(r[3]) : "r"(addr));
}
__device__ __forceinline__ void ldm4t(uint32_t* r, uint32_t addr) {
    asm volatile("ldmatrix.sync.aligned.m8n8.x4.trans.shared.b16 {%0,%1,%2,%3}, [%4];"
        : "=r"(r[0]), "=r"(r[1]), "=r"(r[2]), "=r"(r[3]) : "r"(addr));
}
__device__ __forceinline__ void mma16816(float* d, const uint32_t* a, const uint32_t* b) {
    asm volatile(
        "mma.sync.aligned.m16n8k16.row.col.f32.bf16.bf16.f32 "
        "{%0,%1,%2,%3}, {%4,%5,%6,%7}, {%8,%9}, {%0,%1,%2,%3};"
        : "+f"(d[0]), "+f"(d[1]), "+f"(d[2]), "+f"(d[3])
        : "r"(a[0]), "r"(a[1]), "r"(a[2]), "r"(a[3]), "r"(b[0]), "r"(b[1]));
}

// ---------------- HMMA GEMM ----------------
// C(optional) = act(alpha*(Ah+Al)@B + bias(+bias2) + beta*C + rscale*resid); mirrors optional.
// acc = Ah*Bh + Ah*Bl + Al*Bh.  A: [M][K] row-major hi/lo.
// B: TRB=false -> [N][K] K-major; TRB=true -> [K][N] row-major (ldmatrix.trans).
// bias is offset by zo*sBias (fused-QKV support).
template<int BM, int BN, int NWM, int NWN, bool TRB>
__global__ void __launch_bounds__(NWM*NWN*32)
mma_gemm(const bf16* __restrict__ Ah_, const bf16* __restrict__ Al_,
         const bf16* __restrict__ Bh_, const bf16* __restrict__ Bl_,
         float* __restrict__ C,
         int K, int lda, int ldb, int ldc,
         long long sAo, long long sAi, long long sBo, long long sBi,
         long long sCo, long long sCi, int inner,
         float alpha, const float* __restrict__ bias, long long sBias,
         const float* __restrict__ bias2,
         const float* __restrict__ resid, float rscale, int beta, int act,
         bf16* outh, bf16* outl)
{
    constexpr int TH = NWM * NWN * 32;
    constexpr int WN = BN / NWN;
    constexpr int NF = WN / 8;
    constexpr int ACH = BM * 4;
    constexpr int BCH = BN * 4;
    constexpr int CPR = BN / 8;
    constexpr int STAGE = (BM + BN) * 128;

    extern __shared__ char smem[];
    uint32_t sb = smem_u32(smem);

    int z = blockIdx.z, zo = z / inner, zi = z - zo * inner;
    long long aoff = zo * sAo + zi * sAi;
    long long boff = zo * sBo + zi * sBi;
    Ah_ += aoff; Al_ += aoff;
    Bh_ += boff; Bl_ += boff;
    long long coff = zo * sCo + zi * sCi;
    if (C) C += coff;
    if (resid) resid += coff;
    if (outh) { outh += coff; outl += coff; }
    if (bias) bias += zo * sBias;

    int tid = threadIdx.x, wid = tid >> 5, lane = tid & 31;
    int wm = wid % NWM, wn = wid / NWM;
    int row0 = blockIdx.y * BM, col0 = blockIdx.x * BN;

    auto loadStage = [&](int k0, int st) {
        uint32_t sbase = sb + st * STAGE;
#pragma unroll
        for (int idx = tid; idx < ACH; idx += TH) {
            int r = idx >> 2, c = idx & 3;
            int cs = c ^ ((r >> 1) & 3);
            uint32_t so = sbase + (uint32_t)(r * 4 + cs) * 16;
            long long g = (long long)(row0 + r) * lda + k0 + c * 8;
            cp16(so,           Ah_ + g);
            cp16(so + BM * 64, Al_ + g);
        }
        if (!TRB) {
#pragma unroll
            for (int idx = tid; idx < BCH; idx += TH) {
                int r = idx >> 2, c = idx & 3;
                int cs = c ^ ((r >> 1) & 3);
                uint32_t so = sbase + BM * 128 + (uint32_t)(r * 4 + cs) * 16;
                long long g = (long long)(col0 + r) * ldb + k0 + c * 8;
                cp16(so,           Bh_ + g);
                cp16(so + BN * 64, Bl_ + g);
            }
        } else {
#pragma unroll
            for (int idx = tid; idx < BCH; idx += TH) {
                int r = idx / CPR, c = idx % CPR;
                int cs = c ^ (r & 7);
                uint32_t so = sbase + BM * 128 + (uint32_t)(r * CPR + cs) * 16;
                long long g = (long long)(k0 + r) * ldb + col0 + c * 8;
                cp16(so,           Bh_ + g);
                cp16(so + BN * 64, Bl_ + g);
            }
        }
        asm volatile("cp.async.commit_group;");
    };

    float acc[2][NF][4];
#pragma unroll
    for (int i = 0; i < 2; i++)
#pragma unroll
        for (int j = 0; j < NF; j++)
#pragma unroll
            for (int q = 0; q < 4; q++) acc[i][j][q] = 0.f;

    int nch = K / 32;
    loadStage(0, 0);
    if (nch > 1) loadStage(32, 1);

    for (int s = 0; s < nch; s++) {
        __syncthreads();
        if (s + 2 < nch) {
            loadStage((s + 2) * 32, (s + 2) % 3);
            asm volatile("cp.async.wait_group 2;");
        } else if (s + 1 < nch) {
            asm volatile("cp.async.wait_group 1;");
        } else {
            asm volatile("cp.async.wait_group 0;");
        }
        __syncthreads();
        uint32_t sbase = sb + (s % 3) * STAGE;
#pragma unroll
        for (int ks = 0; ks < 2; ks++) {
            uint32_t ah[2][4], al[2][4];
#pragma unroll
            for (int mf = 0; mf < 2; mf++) {
                int row = wm * 32 + mf * 16 + (lane & 15);
                int c = ks * 2 + (lane >> 4);
                int cs = c ^ ((row >> 1) & 3);
                uint32_t ad = sbase + (uint32_t)(row * 4 + cs) * 16;
                ldm4(ah[mf], ad);
                ldm4(al[mf], ad + BM * 64);
            }
            uint32_t bh[NF][2], bl[NF][2];
            if (!TRB) {
#pragma unroll
                for (int nf = 0; nf < NF; nf += 2) {
                    int rown = wn * WN + nf * 8 + (lane >> 4) * 8 + (lane & 7);
                    int c = ks * 2 + ((lane >> 3) & 1);
                    int cs = c ^ ((rown >> 1) & 3);
                    uint32_t bd = sbase + BM * 128 + (uint32_t)(rown * 4 + cs) * 16;
                    uint32_t t[4];
                    ldm4(t, bd);
                    bh[nf][0] = t[0]; bh[nf][1] = t[1]; bh[nf+1][0] = t[2]; bh[nf+1][1] = t[3];
                    ldm4(t, bd + BN * 64);
                    bl[nf][0] = t[0]; bl[nf][1] = t[1]; bl[nf+1][0] = t[2]; bl[nf+1][1] = t[3];
                }
            } else {
#pragma unroll
                for (int nf = 0; nf < NF; nf += 2) {
                    int n0 = wn * WN + nf * 8;
                    int k = ks * 16 + (lane & 7) + ((lane >> 3) & 1) * 8;
                    int c = (n0 >> 3) + (lane >> 4);
                    int cs = c ^ (k & 7);
                    uint32_t bd = sbase + BM * 128 + (uint32_t)(k * CPR + cs) * 16;
                    uint32_t t[4];
                    ldm4t(t, bd);
                    bh[nf][0] = t[0]; bh[nf][1] = t[1]; bh[nf+1][0] = t[2]; bh[nf+1][1] = t[3];
                    ldm4t(t, bd + BN * 64);
                    bl[nf][0] = t[0]; bl[nf][1] = t[1]; bl[nf+1][0] = t[2]; bl[nf+1][1] = t[3];
                }
            }
#pragma unroll
            for (int mf = 0; mf < 2; mf++)
#pragma unroll
                for (int nf = 0; nf < NF; nf++) {
                    mma16816(acc[mf][nf], ah[mf], bh[nf]);
                    mma16816(acc[mf][nf], ah[mf], bl[nf]);
                    mma16816(acc[mf][nf], al[mf], bh[nf]);
                }
        }
    }

    // ---- epilogue ----
    auto epi2 = [&](int r, int c, float v0, float v1) {
        long long off = (long long)r * ldc + c;
        v0 *= alpha; v1 *= alpha;
        if (bias)  { float2 b2 = *(const float2*)&bias[c];  v0 += b2.x; v1 += b2.y; }
        if (bias2) { float2 b2 = *(const float2*)&bias2[c]; v0 += b2.x; v1 += b2.y; }
        if (beta)  { float2 c2 = *(const float2*)&C[off];   v0 += c2.x; v1 += c2.y; }
        if (resid) { float2 r2 = *(const float2*)&resid[off]; v0 += rscale * r2.x; v1 += rscale * r2.y; }
        if (act) {
            v0 = 0.5f * v0 * (1.f + erff(v0 * 0.70710678118654752f));
            v1 = 0.5f * v1 * (1.f + erff(v1 * 0.70710678118654752f));
        }
        if (C) *(float2*)&C[off] = make_float2(v0, v1);
        if (outh) {
            bf16 h0 = __float2bfloat16(v0), h1 = __float2bfloat16(v1);
            *(bf162*)&outh[off] = bf162(h0, h1);
            *(bf162*)&outl[off] = bf162(__float2bfloat16(v0 - __bfloat162float(h0)),
                                        __float2bfloat16(v1 - __bfloat162float(h1)));
        }
    };
#pragma unroll
    for (int mf = 0; mf < 2; mf++) {
        int r0 = row0 + wm * 32 + mf * 16 + (lane >> 2);
#pragma unroll
        for (int nf = 0; nf < NF; nf++) {
            int c = col0 + wn * WN + nf * 8 + (lane & 3) * 2;
            epi2(r0,     c, acc[mf][nf][0], acc[mf][nf][1]);
            epi2(r0 + 8, c, acc[mf][nf][2], acc[mf][nf][3]);
        }
    }
}

// ---------------- vectorized fp32 -> bf16 hi/lo convert ----------------
__global__ void cvt4_k(const float* __restrict__ x, bf16* __restrict__ h, bf16* __restrict__ l, int n)
{
    int i = (blockIdx.x * 256 + threadIdx.x) * 4;
    if (i >= n) return;
    float4 v = *(const float4*)(x + i);
    bf16 h0 = __float2bfloat16(v.x), h1 = __float2bfloat16(v.y);
    bf16 h2 = __float2bfloat16(v.z), h3 = __float2bfloat16(v.w);
    *(bf162*)(h + i)     = bf162(h0, h1);
    *(bf162*)(h + i + 2) = bf162(h2, h3);
    *(bf162*)(l + i)     = bf162(__float2bfloat16(v.x - __bfloat162float(h0)),
                                 __float2bfloat16(v.y - __bfloat162float(h1)));
    *(bf162*)(l + i + 2) = bf162(__float2bfloat16(v.z - __bfloat162float(h2)),
                                 __float2bfloat16(v.w - __bfloat162float(h3)));
}

// ---------------- softmax over 256-wide rows -> bf16 hi/lo mirrors ----------------
__global__ void softmax256_k(const float* __restrict__ x, bf16* __restrict__ oh, bf16* __restrict__ ol)
{
    __shared__ float red[8];
    __shared__ float bc[2];
    int t = threadIdx.x;
    const float* p = x + (long long)blockIdx.x * 256;
    float v = p[t];
    float m = v;
#pragma unroll
    for (int o = 16; o; o >>= 1) m = fmaxf(m, __shfl_xor_sync(0xffffffffu, m, o));
    if ((t & 31) == 0) red[t >> 5] = m;
    __syncthreads();
    if (t == 0) { float mm = red[0]; for (int i = 1; i < 8; i++) mm = fmaxf(mm, red[i]); bc[0] = mm; }
    __syncthreads();
    float e = expf(v - bc[0]);
    float s = e;
#pragma unroll
    for (int o = 16; o; o >>= 1) s += __shfl_xor_sync(0xffffffffu, s, o);
    if ((t & 31) == 0) red[t >> 5] = s;
    __syncthreads();
    if (t == 0) { float tt = 0.f; for (int i = 0; i < 8; i++) tt += red[i]; bc[1] = 1.f / tt; }
    __syncthreads();
    float val = e * bc[1];
    long long o = (long long)blockIdx.x * 256 + t;
    bf16 hh = __float2bfloat16(val);
    oh[o] = hh;
    ol[o] = __float2bfloat16(val - __bfloat162float(hh));
}

// ---------------- LayerNorm 512 wide: y = LN(x (+ r)) * g + b; mirrors at row*ldm+moff ----------------
__global__ void ln512_k(const float* __restrict__ x, const float* r,
                        float* y, const float* __restrict__ g, const float* __restrict__ bb,
                        bf16* oh, bf16* ol, int ldm, int moff)
{
    __shared__ float red[8];
    __shared__ float bc;
    long long row = blockIdx.x;
    int t = threadIdx.x;
    const float* px = x + row * 512;
    float v0 = px[t], v1 = px[t + 256];
    if (r) { const float* pr = r + row * 512; v0 += pr[t]; v1 += pr[t + 256]; }
    float s = v0 + v1;
#pragma unroll
    for (int o = 16; o; o >>= 1) s += __shfl_xor_sync(0xffffffffu, s, o);
    if ((t & 31) == 0) red[t >> 5] = s;
    __syncthreads();
    if (t == 0) { float tt = 0.f; for (int i = 0; i < 8; i++) tt += red[i]; bc = tt * (1.f / 512.f); }
    __syncthreads();
    float mean = bc;
    float d0 = v0 - mean, d1 = v1 - mean;
    float q = d0 * d0 + d1 * d1;
#pragma unroll
    for (int o = 16; o; o >>= 1) q += __shfl_xor_sync(0xffffffffu, q, o);
    if ((t & 31) == 0) red[t >> 5] = q;
    __syncthreads();
    if (t == 0) { float tt = 0.f; for (int i = 0; i < 8; i++) tt += red[i]; bc = tt * (1.f / 512.f); }
    __syncthreads();
    float inv = rsqrtf(bc + 1e-5f);
    float y0 = d0 * inv * g[t]       + bb[t];
    float y1 = d1 * inv * g[t + 256] + bb[t + 256];
    float* py = y + row * 512;
    py[t] = y0;  py[t + 256] = y1;
    if (oh) {
        long long mo = row * ldm + moff;
        bf16 h0 = __float2bfloat16(y0), h1 = __float2bfloat16(y1);
        oh[mo + t] = h0;       ol[mo + t] = __float2bfloat16(y0 - __bfloat162float(h0));
        oh[mo + t + 256] = h1; ol[mo + t + 256] = __float2bfloat16(y1 - __bfloat162float(h1));
    }
}

// ---------------- L2 normalize 512-wide, fp32 in place + bf16 mirrors ----------------
__global__ void l2n_k(float* x, bf16* oh, bf16* ol)
{
    __shared__ float red[8];
    __shared__ float bc;
    long long row = blockIdx.x;
    int t = threadIdx.x;
    float* p = x + row * 512;
    float v0 = p[t], v1 = p[t + 256];
    float q = v0 * v0 + v1 * v1;
#pragma unroll
    for (int o = 16; o; o >>= 1) q += __shfl_xor_sync(0xffffffffu, q, o);
    if ((t & 31) == 0) red[t >> 5] = q;
    __syncthreads();
    if (t == 0) { float tt = 0.f; for (int i = 0; i < 8; i++) tt += red[i];
                  bc = 1.f / fmaxf(sqrtf(tt), 1e-12f); }
    __syncthreads();
    v0 *= bc; v1 *= bc;
    p[t] = v0; p[t + 256] = v1;
    bf16 h0 = __float2bfloat16(v0), h1 = __float2bfloat16(v1);
    oh[row * 512 + t] = h0;       ol[row * 512 + t] = __float2bfloat16(v0 - __bfloat162float(h0));
    oh[row * 512 + t + 256] = h1; ol[row * 512 + t + 256] = __float2bfloat16(v1 - __bfloat162float(h1));
}

// ---------------- DTW wavefront DP ----------------
__global__ void dtw_k(const float* __restrict__ sim, float* score)
{
    __shared__ float buf[3][SEQ + 1];
    int b = blockIdx.x;
    const float* S = sim + (long long)b * SEQ * SEQ;
    int t = threadIdx.x;
    float *dm2 = buf[0], *dm1 = buf[1], *dc = buf[2];
    if (t == 0) { buf[0][0] = 0.f; buf[1][0] = NEGV; buf[1][1] = NEGV; }
    __syncthreads();
    for (int td = 2; td <= 2 * SEQ; td++) {
        int i = t + 1;
        int j = td - i;
        float val = 0.f;
        bool active = (j >= 1 && j <= SEQ);
        if (active) {
            float dg = dm2[i - 1];
            float up = dm1[i - 1];
            float lf = dm1[i];
            val = S[(i - 1) * SEQ + (j - 1)] + fmaxf(dg, fmaxf(up, lf));
            dc[i] = val;
        }
        if (t == 0 && td <= SEQ) { dc[0] = NEGV; dc[td] = NEGV; }
        if (td == 2 * SEQ && i == SEQ) score[b] = val;
        __syncthreads();
        float* tmp = dm2; dm2 = dm1; dm1 = dc; dc = tmp;
    }
}

// ---------------- host-side launch helper ----------------
template<bool TRB>
static void tcgT(const bf16* Ah, const bf16* Al, const bf16* Bh, const bf16* Bl,
                 float* C, int M, int N, int K, int lda, int ldb, int ldc,
                 long long sAo, long long sAi, long long sBo, long long sBi,
                 long long sCo, long long sCi, int inner, int batch,
                 float alpha, const float* bias, long long sBias, const float* bias2,
                 const float* resid, float rs, int beta, int act,
                 bf16* outh, bf16* outl)
{
    static const int cand[3][2] = { {128,128}, {64,128}, {64,64} };
    int chosen = -1, best = -1;
    long long bestC = -1;
    for (int i = 0; i < 3; i++) {
        int bm = cand[i][0], bn = cand[i][1];
        if (M % bm || N % bn) continue;
        long long c = (long long)(M / bm) * (N / bn) * batch;
        if (c >= 240) { chosen = i; break; }
        if (c > bestC) { bestC = c; best = i; }
    }
    if (chosen < 0) chosen = best;
    if (chosen == 0) {
        constexpr int SM = 3 * (128 + 128) * 128;
        cudaFuncSetAttribute(mma_gemm<128,128,4,2,TRB>, cudaFuncAttributeMaxDynamicSharedMemorySize, SM);
        mma_gemm<128,128,4,2,TRB><<<dim3(N/128, M/128, batch), 256, SM>>>(
            Ah, Al, Bh, Bl, C, K, lda, ldb, ldc, sAo, sAi, sBo, sBi, sCo, sCi, inner,
            alpha, bias, sBias, bias2, resid, rs, beta, act, outh, outl);
    } else if (chosen == 1) {
        constexpr int SM = 3 * (64 + 128) * 128;
        cudaFuncSetAttribute(mma_gemm<64,128,2,2,TRB>, cudaFuncAttributeMaxDynamicSharedMemorySize, SM);
        mma_gemm<64,128,2,2,TRB><<<dim3(N/128, M/64, batch), 128, SM>>>(
            Ah, Al, Bh, Bl, C, K, lda, ldb, ldc, sAo, sAi, sBo, sBi, sCo, sCi, inner,
            alpha, bias, sBias, bias2, resid, rs, beta, act, outh, outl);
    } else {
        constexpr int SM = 3 * (64 + 64) * 128;
        cudaFuncSetAttribute(mma_gemm<64,64,2,2,TRB>, cudaFuncAttributeMaxDynamicSharedMemorySize, SM);
        mma_gemm<64,64,2,2,TRB><<<dim3(N/64, M/64, batch), 128, SM>>>(
            Ah, Al, Bh, Bl, C, K, lda, ldb, ldc, sAo, sAi, sBo, sBi, sCo, sCi, inner,
            alpha, bias, sBias, bias2, resid, rs, beta, act, outh, outl);
    }
}

// weight GEMM: B native [K][N], ldb = N
static void wgemm(const bf16* Ah, const bf16* Al, const bf16* Bh, const bf16* Bl,
                  float* C, int M, int N, int K,
                  float alpha, const float* bias, const float* bias2, int beta, int act,
                  bf16* outh, bf16* outl, int lda = -1)
{
    if (lda < 0) lda = K;
    tcgT<true>(Ah, Al, Bh, Bl, C, M, N, K, lda, N, N, 0, 0, 0, 0, 0, 0, 1, 1,
               alpha, bias, 0, bias2, nullptr, 0.f, beta, act, outh, outl);
}

extern "C" void kernel_launch(void* const* d_in, const int* in_sizes, int n_in,
                              void* d_out, int out_size)
{
    const float* audio  = (const float*)d_in[0];
    const float* video  = (const float*)d_in[1];
    const float* ap_w   = (const float*)d_in[2];
    const float* ap_b   = (const float*)d_in[3];
    const float* vp_w   = (const float*)d_in[4];
    const float* vp_b   = (const float*)d_in[5];
    const float* dtw_w  = (const float*)d_in[6];
    const float* dtw_b  = (const float*)d_in[7];
    const float* mod_emb= (const float*)d_in[8];
    const float* ca_w   = (const float*)d_in[9];
    const float* ca_b   = (const float*)d_in[10];
    const float* sa_w   = (const float*)d_in[11];
    const float* sa_b   = (const float*)d_in[12];
    const float* ln_g   = (const float*)d_in[13];
    const float* ln_b   = (const float*)d_in[14];
    const float* ffn_w1 = (const float*)d_in[15];
    const float* ffn_b1 = (const float*)d_in[16];
    const float* ffn_w2 = (const float*)d_in[17];
    const float* ffn_b2 = (const float*)d_in[18];
    const float* out_w  = (const float*)d_in[19];
    const float* out_b  = (const float*)d_in[20];
    const float* fln_g  = (const float*)d_in[21];
    const float* fln_b  = (const float*)d_in[22];

    float *pa,*pv,*pv2,*pq,*pk,*pt,*psc,*psim;
    cudaGetSymbolAddress((void**)&pa,  g_a);
    cudaGetSymbolAddress((void**)&pv,  g_v);
    cudaGetSymbolAddress((void**)&pv2, g_v2);
    cudaGetSymbolAddress((void**)&pq,  g_q);
    cudaGetSymbolAddress((void**)&pk,  g_k);
    cudaGetSymbolAddress((void**)&pt,  g_t);
    cudaGetSymbolAddress((void**)&psc, g_sc);
    cudaGetSymbolAddress((void**)&psim,g_sim);

    bf16 *audh,*audl,*vidh,*vidl,*ah,*al,*vh,*vl,*v2h,*v2l,*qh,*ql,*kh,*kl;
    bf16 *qkvh,*qkvl,*ctxh,*ctxl,*hh,*hl,*sch,*scl,*simh,*siml,*cath,*catl;
    bf16 *aph,*apl,*vph,*vpl,*dtwh,*dtwl,*cah,*cal,*sah,*sal,*f1h,*f1l,*f2h,*f2l,*owh,*owl;
    cudaGetSymbolAddress((void**)&audh, m_audh); cudaGetSymbolAddress((void**)&audl, m_audl);
    cudaGetSymbolAddress((void**)&vidh, m_vidh); cudaGetSymbolAddress((void**)&vidl, m_vidl);
    cudaGetSymbolAddress((void**)&ah, m_ah);     cudaGetSymbolAddress((void**)&al, m_al);
    cudaGetSymbolAddress((void**)&vh, m_vh);     cudaGetSymbolAddress((void**)&vl, m_vl);
    cudaGetSymbolAddress((void**)&v2h, m_v2h);   cudaGetSymbolAddress((void**)&v2l, m_v2l);
    cudaGetSymbolAddress((void**)&qh, m_qh);     cudaGetSymbolAddress((void**)&ql, m_ql);
    cudaGetSymbolAddress((void**)&kh, m_kh);     cudaGetSymbolAddress((void**)&kl, m_kl);
    cudaGetSymbolAddress((void**)&qkvh, m_qkvh); cudaGetSymbolAddress((void**)&qkvl, m_qkvl);
    cudaGetSymbolAddress((void**)&ctxh, m_ctxh); cudaGetSymbolAddress((void**)&ctxl, m_ctxl);
    cudaGetSymbolAddress((void**)&hh, m_hh);     cudaGetSymbolAddress((void**)&hl, m_hl);
    cudaGetSymbolAddress((void**)&sch, m_sch);   cudaGetSymbolAddress((void**)&scl, m_scl);
    cudaGetSymbolAddress((void**)&simh, m_simh); cudaGetSymbolAddress((void**)&siml, m_siml);
    cudaGetSymbolAddress((void**)&cath, m_cath); cudaGetSymbolAddress((void**)&catl, m_catl);
    cudaGetSymbolAddress((void**)&aph, c_aph);   cudaGetSymbolAddress((void**)&apl, c_apl);
    cudaGetSymbolAddress((void**)&vph, c_vph);   cudaGetSymbolAddress((void**)&vpl, c_vpl);
    cudaGetSymbolAddress((void**)&dtwh, c_dtwh); cudaGetSymbolAddress((void**)&dtwl, c_dtwl);
    cudaGetSymbolAddress((void**)&cah, c_cah);   cudaGetSymbolAddress((void**)&cal, c_cal);
    cudaGetSymbolAddress((void**)&sah, c_sah);   cudaGetSymbolAddress((void**)&sal, c_sal);
    cudaGetSymbolAddress((void**)&f1h, c_f1h);   cudaGetSymbolAddress((void**)&f1l, c_f1l);
    cudaGetSymbolAddress((void**)&f2h, c_f2h);   cudaGetSymbolAddress((void**)&f2l, c_f2l);
    cudaGetSymbolAddress((void**)&owh, c_oh);    cudaGetSymbolAddress((void**)&owl, c_ol);

    float* out = (float*)d_out;
    float* out_score = out + (out_size - NB);

    const long long SD  = (long long)SEQ * DIM;
    const long long SS  = (long long)SEQ * SEQ;
    const long long W   = (long long)DIM * DIM;
    const long long QKV = (long long)ROWS * DIM;   // per-z stride in fused qkv buffer

    auto cv = [&](const float* x, bf16* h, bf16* l, long long n) {
        cvt4_k<<<(int)((n / 4 + 255) / 256), 256>>>(x, h, l, (int)n);
    };

    // ---- weight + input converts ----
    cv(ap_w,  aph, apl, 512*512);
    cv(vp_w,  vph, vpl, 256*512);
    cv(dtw_w, dtwh, dtwl, 512*512);
    cv(ca_w,  cah, cal, 32ll*512*512);
    cv(sa_w,  sah, sal, 32ll*512*512);
    cv(ffn_w1, f1h, f1l, 8ll*512*2048);
    cv(ffn_w2, f2h, f2l, 8ll*2048*512);
    cv(out_w, owh, owl, 1024*512);
    cv(audio, audh, audl, (long long)ROWS*DIM);
    cv(video, vidh, vidl, (long long)ROWS*256);

    // ---- projections + modality embeddings ----
    wgemm(audh, audl, aph, apl, pa, ROWS, DIM, DIM, 1.f, ap_b, mod_emb,       0, 0, ah, al);
    wgemm(vidh, vidl, vph, vpl, pv, ROWS, DIM, 256, 1.f, vp_b, mod_emb + DIM, 0, 0, vh, vl);

    // ---- DTW similarity ----
    wgemm(ah, al, dtwh, dtwl, pq, ROWS, DIM, DIM, 1.f, dtw_b, nullptr, 0, 0, nullptr, nullptr);
    wgemm(vh, vl, dtwh, dtwl, pk, ROWS, DIM, DIM, 1.f, dtw_b, nullptr, 0, 0, nullptr, nullptr);
    l2n_k<<<ROWS, 256>>>(pq, qh, ql);
    l2n_k<<<ROWS, 256>>>(pk, kh, kl);
    tcgT<false>(qh, ql, kh, kl, psim, SEQ, SEQ, DIM, DIM, DIM, SEQ,
                SD, 0, SD, 0, SS, 0, 1, NB,
                1.f, nullptr, 0, nullptr, nullptr, 0.f, 0, 0, nullptr, nullptr);
    dtw_k<<<NB, 256>>>(psim, out_score);
    softmax256_k<<<NB*SEQ, 256>>>(psim, simh, siml);
    // v2 = 0.5*v + 0.5*softmax(sim) @ v
    tcgT<true>(simh, siml, vh, vl, pv2, SEQ, DIM, SEQ, SEQ, DIM, DIM,
               SS, 0, SD, 0, SD, 0, 1, NB,
               0.5f, nullptr, 0, nullptr, pv, 0.5f, 0, 0, v2h, v2l);

    float* a = pa;
    float* v = pv2;
    bf16 *a_h = ah, *a_l = al, *v_h = v2h, *v_l = v2l;

    // fused QKV mirrors: qkv + 0 = Q, + QKV = K, + 2*QKV = V
    auto mha = [&](float* x, bf16* x_h, bf16* x_l, bf16* kv_h, bf16* kv_l, bool self,
                   const bf16* Wh, const bf16* Wl, const float* bb,
                   const float* lg, const float* lb) {
        if (self) {
            // Q,K,V in one launch: z batches the 3 weight mats
            tcgT<true>(x_h, x_l, Wh, Wl, nullptr, ROWS, DIM, DIM, DIM, DIM, DIM,
                       0, 0, W, 0, QKV, 0, 1, 3,
                       1.f, bb, DIM, nullptr, nullptr, 0.f, 0, 0, qkvh, qkvl);
        } else {
            tcgT<true>(x_h, x_l, Wh, Wl, nullptr, ROWS, DIM, DIM, DIM, DIM, DIM,
                       0, 0, 0, 0, 0, 0, 1, 1,
                       1.f, bb, 0, nullptr, nullptr, 0.f, 0, 0, qkvh, qkvl);
            tcgT<true>(kv_h, kv_l, Wh + W, Wl + W, nullptr, ROWS, DIM, DIM, DIM, DIM, DIM,
                       0, 0, W, 0, QKV, 0, 1, 2,
                       1.f, bb + DIM, DIM, nullptr, nullptr, 0.f, 0, 0, qkvh + QKV, qkvl + QKV);
        }
        // scores[b,h] = (1/8) Q_bh @ K_bh^T
        tcgT<false>(qkvh, qkvl, qkvh + QKV, qkvl + QKV, psc, SEQ, SEQ, HDIM, DIM, DIM, SEQ,
                    SD, HDIM, SD, HDIM, (long long)NH*SS, SS, NH, NB*NH,
                    0.125f, nullptr, 0, nullptr, nullptr, 0.f, 0, 0, nullptr, nullptr);
        softmax256_k<<<NB*NH*SEQ, 256>>>(psc, sch, scl);
        // ctx[b,h] = P @ V_bh (row-major V, head col-slice, TRB)
        tcgT<true>(sch, scl, qkvh + 2*QKV, qkvl + 2*QKV, nullptr, SEQ, HDIM, SEQ, SEQ, DIM, DIM,
                   (long long)NH*SS, SS, SD, HDIM, SD, HDIM, NH, NB*NH,
                   1.f, nullptr, 0, nullptr, nullptr, 0.f, 0, 0, ctxh, ctxl);
        wgemm(ctxh, ctxl, Wh + 3*W, Wl + 3*W, pt, ROWS, DIM, DIM, 1.f, bb + 3*DIM, nullptr, 0, 0, nullptr, nullptr);
        ln512_k<<<ROWS, 256>>>(pt, x, x, lg, lb, x_h, x_l, 512, 0);
    };

    auto ffn = [&](float* x, bf16* x_h, bf16* x_l, int idx,
                   const float* lg, const float* lb,
                   bf16* mh, bf16* ml, int ldm, int moff) {
        const bf16* w1h = f1h + (long long)idx * 512 * 2048;
        const bf16* w1l = f1l + (long long)idx * 512 * 2048;
        const bf16* w2h = f2h + (long long)idx * 2048 * 512;
        const bf16* w2l = f2l + (long long)idx * 2048 * 512;
        wgemm(x_h, x_l, w1h, w1l, nullptr, ROWS, 4*DIM, DIM, 1.f, ffn_b1 + (long long)idx*4*DIM, nullptr, 0, 1, hh, hl);
        wgemm(hh,  hl,  w2h, w2l, pt, ROWS, DIM, 4*DIM, 1.f, ffn_b2 + (long long)idx*DIM, nullptr, 0, 0, nullptr, nullptr);
        ln512_k<<<ROWS, 256>>>(pt, x, x, lg, lb, mh, ml, ldm, moff);
    };

    for (int l = 0; l < NLAYER; l++) {
        const bf16* caw0h = cah + (long long)((l*2+0)*4) * W;  const bf16* caw0l = cal + (long long)((l*2+0)*4) * W;
        const bf16* caw1h = cah + (long long)((l*2+1)*4) * W;  const bf16* caw1l = cal + (long long)((l*2+1)*4) * W;
        const bf16* saw0h = sah + (long long)((l*2+0)*4) * W;  const bf16* saw0l = sal + (long long)((l*2+0)*4) * W;
        const bf16* saw1h = sah + (long long)((l*2+1)*4) * W;  const bf16* saw1l = sal + (long long)((l*2+1)*4) * W;
        const float* cab0 = ca_b + (long long)((l*2+0)*4) * DIM;
        const float* cab1 = ca_b + (long long)((l*2+1)*4) * DIM;
        const float* sab0 = sa_b + (long long)((l*2+0)*4) * DIM;
        const float* sab1 = sa_b + (long long)((l*2+1)*4) * DIM;
        const float* lg = ln_g + (long long)l * 6 * DIM;
        const float* lb = ln_b + (long long)l * 6 * DIM;
        bool last = (l == NLAYER - 1);

        mha(a, a_h, a_l, v_h, v_l, false, caw0h, caw0l, cab0, lg + 0*DIM, lb + 0*DIM);
        mha(v, v_h, v_l, a_h, a_l, false, caw1h, caw1l, cab1, lg + 3*DIM, lb + 3*DIM);
        mha(a, a_h, a_l, a_h, a_l, true,  saw0h, saw0l, sab0, lg + 1*DIM, lb + 1*DIM);
        mha(v, v_h, v_l, v_h, v_l, true,  saw1h, saw1l, sab1, lg + 4*DIM, lb + 4*DIM);
        if (!last) {
            ffn(a, a_h, a_l, l*2+0, lg + 2*DIM, lb + 2*DIM, a_h, a_l, 512, 0);
            ffn(v, v_h, v_l, l*2+1, lg + 5*DIM, lb + 5*DIM, v_h, v_l, 512, 0);
        } else {
            // final layer: mirrors go into the concat buffer for the fused head GEMM
            ffn(a, a_h, a_l, l*2+0, lg + 2*DIM, lb + 2*DIM, cath, catl, 1024, 0);
            ffn(v, v_h, v_l, l*2+1, lg + 5*DIM, lb + 5*DIM, cath, catl, 1024, 512);
        }
    }

    // ---- fused head: [a | v] @ out_w + out_b (single K=1024 GEMM), then LN -> d_out ----
    wgemm(cath, catl, owh, owl, pq, ROWS, DIM, 1024, 1.f, out_b, nullptr, 0, 0, nullptr, nullptr, 1024);
    ln512_k<<<ROWS, 256>>>(pq, nullptr, out, fln_g, fln_b, nullptr, nullptr, 512, 0);
}